// round 5
// baseline (speedup 1.0000x reference)
#include <cuda_runtime.h>
#include <math.h>

#define HID 256
#define NH 4
#define HD 64
#define NL 2
#define TOUT 12
#define MAXN 24000
#define MAXE 400000

// ---------------- scratch (static device globals; no allocation) ----------------
__device__ float g_xl[MAXN * HID];
__device__ float g_xr[MAXN * HID];
__device__ float g_fA[MAXN * HID];
__device__ float g_fB[MAXN * HID];
__device__ float g_elog[MAXE * NH];
__device__ int   g_deg[MAXN];
__device__ int   g_off[MAXN + 1];
__device__ int   g_cur[MAXN];
__device__ int   g_eidx[MAXE];
__device__ float g_ctx[MAXN * HID];
__device__ float g_G0[(size_t)MAXN * 1024];
__device__ float g_gates[(size_t)MAXN * 1024];
__device__ float g_c[MAXN * HID];
__device__ float g_prev[MAXN];
__device__ float g_WihT[256 * 1024];
__device__ float g_WhhT[256 * 1024];
__device__ float g_mlpT[256 * 256];
__device__ float g_u[1024];
__device__ float g_bsum[1024];

// ---------------- f32x2 helpers ----------------
__device__ __forceinline__ unsigned long long pk2(float a, float b) {
    unsigned long long r;
    asm("mov.b64 %0, {%1,%2};" : "=l"(r) : "f"(a), "f"(b));
    return r;
}
__device__ __forceinline__ void fmaf2(unsigned long long& c, unsigned long long a, unsigned long long b) {
    asm("fma.rn.f32x2 %0, %1, %2, %0;" : "+l"(c) : "l"(a), "l"(b));
}
__device__ __forceinline__ float2 unpk2(unsigned long long c) {
    float2 f;
    asm("mov.b64 {%0,%1}, %2;" : "=f"(f.x), "=f"(f.y) : "l"(c));
    return f;
}

// ---------------- GEMM: C[M,Nc] = A[M,256] * B[256,Nc] (+Cadd +bias +r*s) ----------------
// A row-major (lda=256), B row-major K-major (ldb=Nc).
template <bool ADDC, bool BIASF, bool RANK1>
__global__ void __launch_bounds__(256, 2)
gemm256(const float* __restrict__ A, const float* __restrict__ B,
        float* __restrict__ C,
        const float* __restrict__ Cadd, const float* __restrict__ bias,
        const float* __restrict__ rvec, const float* __restrict__ svec,
        int M, int Nc)
{
    const int K = 256, BK = 16, BM = 128;
    __shared__ __align__(16) float As[2][BK][BM + 4];
    __shared__ __align__(16) float Bs[2][BK][128];

    int tid = threadIdx.x;
    int m0 = blockIdx.x * BM, n0 = blockIdx.y * 128;
    int tx = tid & 15, ty = tid >> 4;
    int a_row = tid >> 2, a_c = (tid & 3) << 2;
    int b_k = tid >> 5, b_n = (tid & 31) << 2;

    float4 ar[2], br[2];
    auto ldg = [&](int kt) {
#pragma unroll
        for (int p = 0; p < 2; p++) {
            int gm = m0 + a_row + (p << 6);
            ar[p] = (gm < M) ? *(const float4*)(A + (size_t)gm * K + kt * BK + a_c)
                             : make_float4(0.f, 0.f, 0.f, 0.f);
            br[p] = *(const float4*)(B + (size_t)(kt * BK + b_k + (p << 3)) * Nc + n0 + b_n);
        }
    };
    auto sts = [&](int buf) {
#pragma unroll
        for (int p = 0; p < 2; p++) {
            int row = a_row + (p << 6);
            As[buf][a_c + 0][row] = ar[p].x;
            As[buf][a_c + 1][row] = ar[p].y;
            As[buf][a_c + 2][row] = ar[p].z;
            As[buf][a_c + 3][row] = ar[p].w;
            *(float4*)&Bs[buf][b_k + (p << 3)][b_n] = br[p];
        }
    };

    ldg(0);
    sts(0);
    __syncthreads();

    unsigned long long acc[8][4];
#pragma unroll
    for (int r = 0; r < 8; r++)
#pragma unroll
        for (int j = 0; j < 4; j++) acc[r][j] = 0ull;

    const int NT = K / BK;  // 16
    for (int kt = 0; kt < NT; kt++) {
        int buf = kt & 1;
        if (kt + 1 < NT) ldg(kt + 1);
#pragma unroll
        for (int k = 0; k < BK; k++) {
            float4 a0 = *(const float4*)&As[buf][k][ty << 3];
            float4 a1 = *(const float4*)&As[buf][k][(ty << 3) + 4];
            ulonglong2 b0 = *(const ulonglong2*)&Bs[buf][k][tx << 3];
            ulonglong2 b1 = *(const ulonglong2*)&Bs[buf][k][(tx << 3) + 4];
            unsigned long long bb[4] = {b0.x, b0.y, b1.x, b1.y};
            float av[8] = {a0.x, a0.y, a0.z, a0.w, a1.x, a1.y, a1.z, a1.w};
#pragma unroll
            for (int r = 0; r < 8; r++) {
                unsigned long long ap = pk2(av[r], av[r]);
#pragma unroll
                for (int j = 0; j < 4; j++) fmaf2(acc[r][j], ap, bb[j]);
            }
        }
        if (kt + 1 < NT) sts(buf ^ 1);
        __syncthreads();
    }

#pragma unroll
    for (int r = 0; r < 8; r++) {
        int gm = m0 + (ty << 3) + r;
        if (gm >= M) break;
        float rv = RANK1 ? rvec[gm] : 0.f;
#pragma unroll
        for (int j = 0; j < 4; j++) {
            int gn = n0 + (tx << 3) + (j << 1);
            float2 v = unpk2(acc[r][j]);
            if (ADDC) {
                float2 cv = *(const float2*)(Cadd + (size_t)gm * Nc + gn);
                v.x += cv.x; v.y += cv.y;
            }
            if (BIASF) { v.x += bias[gn]; v.y += bias[gn + 1]; }
            if (RANK1) { v.x += rv * svec[gn]; v.y += rv * svec[gn + 1]; }
            *(float2*)(C + (size_t)gm * Nc + gn) = v;
        }
    }
}

// ---------------- CSR build ----------------
__global__ void zero_i_k(int* p, int n) {
    int i = blockIdx.x * 256 + threadIdx.x;
    if (i < n) p[i] = 0;
}
__global__ void zero_f_k(float* p, int n) {
    int i = blockIdx.x * 256 + threadIdx.x;
    if (i < n) p[i] = 0.f;
}
__global__ void count_k(const int* __restrict__ dst, int* __restrict__ deg, int E) {
    int e = blockIdx.x * 256 + threadIdx.x;
    if (e < E) atomicAdd(&deg[dst[e]], 1);
}
__global__ void scan_k(const int* __restrict__ deg, int* __restrict__ off, int* __restrict__ cur, int n) {
    __shared__ int s[1024];
    int t = threadIdx.x;
    int per = (n + 1023) >> 10;
    int b = t * per;
    int e = min(b + per, n);
    int sum = 0;
    for (int i = b; i < e; i++) sum += deg[i];
    s[t] = sum;
    __syncthreads();
    for (int d = 1; d < 1024; d <<= 1) {
        int v = (t >= d) ? s[t - d] : 0;
        __syncthreads();
        s[t] += v;
        __syncthreads();
    }
    int run = s[t] - sum;
    for (int i = b; i < e; i++) { off[i] = run; cur[i] = run; run += deg[i]; }
    if (t == 1023) off[n] = s[1023];
}
__global__ void scatter_k(const int* __restrict__ dst, int* __restrict__ cur, int* __restrict__ eidx, int E) {
    int e = blockIdx.x * 256 + threadIdx.x;
    if (e < E) {
        int p = atomicAdd(&cur[dst[e]], 1);
        eidx[p] = e;
    }
}

// ---------------- weight transforms ----------------
// dst[c*R + r] = src[r*S + O + c]
__global__ void transpose_k(const float* __restrict__ src, float* __restrict__ dst,
                            int R, int C, int S, int O) {
    __shared__ float t[32][33];
    int cb = blockIdx.x * 32, rb = blockIdx.y * 32;
    for (int i = threadIdx.y; i < 32; i += 8) {
        int r = rb + i, c = cb + threadIdx.x;
        t[i][threadIdx.x] = (r < R && c < C) ? src[(size_t)r * S + O + c] : 0.f;
    }
    __syncthreads();
    for (int i = threadIdx.y; i < 32; i += 8) {
        int c = cb + i, r = rb + threadIdx.x;
        if (r < R && c < C) dst[(size_t)c * R + r] = t[threadIdx.x][i];
    }
}
__global__ void uvec_k(const float* __restrict__ WihT, const float* __restrict__ mlp_w,
                       const float* __restrict__ bih, const float* __restrict__ bhh,
                       float* __restrict__ u, float* __restrict__ bsum) {
    int g = blockIdx.x * 256 + threadIdx.x;  // grid 4 -> 1024
    float s = 0.f;
    for (int k = 0; k < 256; k++) s += WihT[k * 1024 + g] * mlp_w[k * 257];
    u[g] = s;
    bsum[g] = bih[g] + bhh[g];
}

// ---------------- GAT edge kernels ----------------
__device__ __forceinline__ float lreluf(float v) { return v > 0.f ? v : 0.2f * v; }
__device__ __forceinline__ float eluf(float v) { return v > 0.f ? v : expm1f(v); }

__global__ void edge_logits_k(const float* __restrict__ xl, const float* __restrict__ xr,
                              const int* __restrict__ src, const int* __restrict__ dst,
                              const float* __restrict__ att, float* __restrict__ elog, int E) {
    __shared__ float satt[HID];
    int tid = threadIdx.x;
    satt[tid] = att[tid];
    __syncthreads();
    int lane = tid & 31, w = tid >> 5;
    int e = blockIdx.x * 8 + w;
    if (e >= E) return;
    int s = src[e], d = dst[e];
    const float4* pa = (const float4*)(xl + (size_t)s * HID + lane * 8);
    const float4* pb = (const float4*)(xr + (size_t)d * HID + lane * 8);
    float4 a0 = pa[0], a1 = pa[1], b0 = pb[0], b1 = pb[1];
    const float* at = satt + lane * 8;
    float p = 0.f;
    p += at[0] * lreluf(a0.x + b0.x);
    p += at[1] * lreluf(a0.y + b0.y);
    p += at[2] * lreluf(a0.z + b0.z);
    p += at[3] * lreluf(a0.w + b0.w);
    p += at[4] * lreluf(a1.x + b1.x);
    p += at[5] * lreluf(a1.y + b1.y);
    p += at[6] * lreluf(a1.z + b1.z);
    p += at[7] * lreluf(a1.w + b1.w);
    p += __shfl_xor_sync(0xffffffffu, p, 1);
    p += __shfl_xor_sync(0xffffffffu, p, 2);
    p += __shfl_xor_sync(0xffffffffu, p, 4);
    if ((lane & 7) == 0) elog[(size_t)e * NH + (lane >> 3)] = expf(p);
}

__global__ void aggregate_k(const float* __restrict__ xl, const float* __restrict__ elog,
                            const int* __restrict__ src,
                            const int* __restrict__ off, const int* __restrict__ eidx,
                            const float* __restrict__ bias, float* __restrict__ xout, int N) {
    int tid = threadIdx.x;
    int lane = tid & 31, w = tid >> 5;
    int n = blockIdx.x * 8 + w;
    if (n >= N) return;
    int beg = off[n], end = off[n + 1];
    int h = lane >> 3;
    float den = 0.f;
    for (int j = beg; j < end; j++) den += elog[(size_t)eidx[j] * NH + h];
    float rin = 1.f / den;
    float a[8];
#pragma unroll
    for (int i = 0; i < 8; i++) a[i] = 0.f;
    for (int j = beg; j < end; j++) {
        int e = eidx[j];
        float wg = elog[(size_t)e * NH + h] * rin;
        const float4* pv = (const float4*)(xl + (size_t)src[e] * HID + lane * 8);
        float4 v0 = pv[0], v1 = pv[1];
        a[0] += wg * v0.x; a[1] += wg * v0.y; a[2] += wg * v0.z; a[3] += wg * v0.w;
        a[4] += wg * v1.x; a[5] += wg * v1.y; a[6] += wg * v1.z; a[7] += wg * v1.w;
    }
    const float* bb = bias + lane * 8;
    float4 o0, o1;
    o0.x = eluf(a[0] + bb[0]); o0.y = eluf(a[1] + bb[1]);
    o0.z = eluf(a[2] + bb[2]); o0.w = eluf(a[3] + bb[3]);
    o1.x = eluf(a[4] + bb[4]); o1.y = eluf(a[5] + bb[5]);
    o1.z = eluf(a[6] + bb[6]); o1.w = eluf(a[7] + bb[7]);
    float4* po = (float4*)(xout + (size_t)n * HID + lane * 8);
    po[0] = o0;
    po[1] = o1;
}

// ---------------- decoder small kernels ----------------
__global__ void rowdot_k(const float* __restrict__ X, const float* __restrict__ w,
                         const float* __restrict__ b, float* __restrict__ out, int N) {
    int wid = blockIdx.x * 8 + (threadIdx.x >> 5);
    int lane = threadIdx.x & 31;
    if (wid >= N) return;
    const float* row = X + (size_t)wid * HID;
    float s = 0.f;
#pragma unroll
    for (int i = 0; i < 8; i++) s += row[lane + i * 32] * w[lane + i * 32];
    for (int d = 16; d; d >>= 1) s += __shfl_xor_sync(0xffffffffu, s, d);
    if (lane == 0) out[wid] = s + b[0];
}

__device__ __forceinline__ float sigm(float x) { return 1.f / (1.f + expf(-x)); }

__global__ void lstm_step_k(const float* __restrict__ gates, float* __restrict__ c,
                            float* __restrict__ h, const float* __restrict__ out_w,
                            const float* __restrict__ out_b,
                            float* __restrict__ prev, float* __restrict__ outp,
                            int step, int N) {
    int n = blockIdx.x;
    int j = threadIdx.x;
    const float* g = gates + (size_t)n * 1024;
    float ig = sigm(g[j]);
    float fg = sigm(g[j + 256]);
    float gg = tanhf(g[j + 512]);
    float og = sigm(g[j + 768]);
    size_t idx = (size_t)n * HID + j;
    float cj = fg * c[idx] + ig * gg;
    c[idx] = cj;
    float hj = og * tanhf(cj);
    h[idx] = hj;
    float v = hj * out_w[j];
#pragma unroll
    for (int d = 16; d; d >>= 1) v += __shfl_xor_sync(0xffffffffu, v, d);
    __shared__ float red[8];
    if ((j & 31) == 0) red[j >> 5] = v;
    __syncthreads();
    if (j == 0) {
        float t = red[0] + red[1] + red[2] + red[3] + red[4] + red[5] + red[6] + red[7] + out_b[0];
        prev[n] = t;
        outp[(size_t)n * TOUT + step] = t;
    }
}

// ---------------- launch ----------------
extern "C" void kernel_launch(void* const* d_in, const int* in_sizes, int n_in,
                              void* d_out, int out_size) {
    const float* x     = (const float*)d_in[0];
    const int*   ei    = (const int*)d_in[1];
    const float* w_src = (const float*)d_in[2];
    const float* w_dst = (const float*)d_in[3];
    const float* att   = (const float*)d_in[4];
    const float* gbias = (const float*)d_in[5];
    const float* mlp_w = (const float*)d_in[6];
    const float* mlp_b = (const float*)d_in[7];
    const float* wih   = (const float*)d_in[8];
    const float* whh   = (const float*)d_in[9];
    const float* bih   = (const float*)d_in[10];
    const float* bhh   = (const float*)d_in[11];
    const float* initw = (const float*)d_in[12];
    const float* initb = (const float*)d_in[13];
    const float* outw  = (const float*)d_in[14];
    const float* outb  = (const float*)d_in[15];
    float* out = (float*)d_out;

    int N = in_sizes[0] / HID;
    int E = in_sizes[1] / 2;

    float *xl, *xr, *fA, *fB, *elog, *ctx, *G0, *gates, *cst, *prev;
    float *WihT, *WhhT, *mlpT, *uv, *bs;
    int *deg, *off, *cur, *eidx;
    cudaGetSymbolAddress((void**)&xl, g_xl);
    cudaGetSymbolAddress((void**)&xr, g_xr);
    cudaGetSymbolAddress((void**)&fA, g_fA);
    cudaGetSymbolAddress((void**)&fB, g_fB);
    cudaGetSymbolAddress((void**)&elog, g_elog);
    cudaGetSymbolAddress((void**)&ctx, g_ctx);
    cudaGetSymbolAddress((void**)&G0, g_G0);
    cudaGetSymbolAddress((void**)&gates, g_gates);
    cudaGetSymbolAddress((void**)&cst, g_c);
    cudaGetSymbolAddress((void**)&prev, g_prev);
    cudaGetSymbolAddress((void**)&WihT, g_WihT);
    cudaGetSymbolAddress((void**)&WhhT, g_WhhT);
    cudaGetSymbolAddress((void**)&mlpT, g_mlpT);
    cudaGetSymbolAddress((void**)&uv, g_u);
    cudaGetSymbolAddress((void**)&bs, g_bsum);
    cudaGetSymbolAddress((void**)&deg, g_deg);
    cudaGetSymbolAddress((void**)&off, g_off);
    cudaGetSymbolAddress((void**)&cur, g_cur);
    cudaGetSymbolAddress((void**)&eidx, g_eidx);

    int eb = (E + 255) / 256;
    int nb = (N + 255) / 256;

    // CSR by destination
    zero_i_k<<<nb, 256>>>(deg, N);
    count_k<<<eb, 256>>>(ei + E, deg, E);
    scan_k<<<1, 1024>>>(deg, off, cur, N);
    scatter_k<<<eb, 256>>>(ei + E, cur, eidx, E);

    // weight transforms
    dim3 tb(32, 8);
    transpose_k<<<dim3(256 / 32, 1024 / 32), tb>>>(wih, WihT, 1024, 256, 256, 0);
    transpose_k<<<dim3(256 / 32, 1024 / 32), tb>>>(whh, WhhT, 1024, 256, 256, 0);
    transpose_k<<<dim3(256 / 32, 256 / 32), tb>>>(mlp_w, mlpT, 256, 256, 257, 1);
    uvec_k<<<4, 256>>>(WihT, mlp_w, bih, bhh, uv, bs);

    int mg = (N + 127) / 128;
    int egrid = (E + 7) / 8;
    int ngrid = (N + 7) / 8;

    // GAT layers
    const float* fin = x;
    float* fouts[2] = {fA, fB};
    for (int l = 0; l < NL; l++) {
        gemm256<false, false, false><<<dim3(mg, 2), 256>>>(
            fin, w_src + (size_t)l * HID * HID, xl, nullptr, nullptr, nullptr, nullptr, N, HID);
        gemm256<false, false, false><<<dim3(mg, 2), 256>>>(
            fin, w_dst + (size_t)l * HID * HID, xr, nullptr, nullptr, nullptr, nullptr, N, HID);
        edge_logits_k<<<egrid, 256>>>(xl, xr, ei, ei + E, att + l * HID, elog, E);
        aggregate_k<<<ngrid, 256>>>(xl, elog, ei, off, eidx, gbias + l * HID, fouts[l], N);
        fin = fouts[l];
    }
    // fin == fB == ctx == h0

    // decoder precompute
    gemm256<false, true, false><<<dim3(mg, 2), 256>>>(
        fin, mlpT, ctx, nullptr, mlp_b, nullptr, nullptr, N, HID);
    gemm256<false, true, false><<<dim3(mg, 8), 256>>>(
        ctx, WihT, G0, nullptr, bs, nullptr, nullptr, N, 1024);
    rowdot_k<<<ngrid, 256>>>(fin, initw, initb, prev, N);
    zero_f_k<<<(N * HID + 255) / 256, 256>>>(cst, N * HID);

    float* h = fouts[1];  // alias: h0 = final GAT features
    for (int s = 0; s < TOUT; s++) {
        gemm256<true, false, true><<<dim3(mg, 8), 256>>>(
            h, WhhT, gates, G0, nullptr, prev, uv, N, 1024);
        lstm_step_k<<<N, 256>>>(gates, cst, h, outw, outb, prev, out, s, N);
    }
}

// round 9
// speedup vs baseline: 1.9530x; 1.9530x over previous
#include <cuda_runtime.h>
#include <cuda_bf16.h>
#include <math.h>
#include <stdint.h>

#define HID 256
#define NH 4
#define NL 2
#define TOUT 12
#define MAXN 24000
#define MAXE 400000

// ---------------- scratch (static device globals; no allocation) ----------------
__device__ float g_xl[MAXN * HID];
__device__ float g_xr[MAXN * HID];
__device__ float g_elog[MAXE * NH];
__device__ int   g_deg[MAXN];
__device__ int   g_off[MAXN + 1];
__device__ int   g_cur[MAXN];
__device__ int   g_eidx[MAXE];
__device__ float g_G0[(size_t)MAXN * 1024];
__device__ float g_c[MAXN * HID];
__device__ float g_prev[MAXN];
__device__ float g_up[1024];
__device__ float g_bsp[1024];

// bf16 split buffers
__device__ __nv_bfloat16 g_s0h[MAXN * HID];
__device__ __nv_bfloat16 g_s0l[MAXN * HID];
__device__ __nv_bfloat16 g_hAh[MAXN * HID];
__device__ __nv_bfloat16 g_hAl[MAXN * HID];
__device__ __nv_bfloat16 g_hBh[MAXN * HID];
__device__ __nv_bfloat16 g_hBl[MAXN * HID];
__device__ __nv_bfloat16 g_csh[MAXN * HID];
__device__ __nv_bfloat16 g_csl[MAXN * HID];
// bf16 weight splits
__device__ __nv_bfloat16 g_wgh[4 * 256 * 256];
__device__ __nv_bfloat16 g_wgl[4 * 256 * 256];
__device__ __nv_bfloat16 g_mbh[256 * 256];
__device__ __nv_bfloat16 g_mbl[256 * 256];
__device__ __nv_bfloat16 g_wihh[1024 * 256];
__device__ __nv_bfloat16 g_wihl[1024 * 256];
__device__ __nv_bfloat16 g_whhh[1024 * 256];
__device__ __nv_bfloat16 g_whhl[1024 * 256];

// ---------------- helpers ----------------
__device__ __forceinline__ uint32_t smem_u32(const void* p) {
    uint32_t a;
    asm("{ .reg .u64 t; cvta.to.shared.u64 t, %1; cvt.u32.u64 %0, t; }" : "=r"(a) : "l"(p));
    return a;
}
__device__ __forceinline__ uint32_t swz(uint32_t b) { return b ^ ((b >> 3) & 0x70); }

__device__ __forceinline__ void splitf(float v, unsigned short& h, unsigned short& l) {
    __nv_bfloat16 hb = __float2bfloat16(v);
    float r = v - __bfloat162float(hb);
    h = __bfloat16_as_ushort(hb);
    l = __bfloat16_as_ushort(__float2bfloat16(r));
}
__device__ __forceinline__ uint32_t pk16(unsigned short a, unsigned short b) {
    return (uint32_t)a | ((uint32_t)b << 16);
}
__device__ __forceinline__ float sigm(float x) { return 1.f / (1.f + expf(-x)); }

#define LDSM4(r, a) \
    asm volatile("ldmatrix.sync.aligned.m8n8.x4.shared.b16 {%0,%1,%2,%3}, [%4];" \
                 : "=r"((r)[0]), "=r"((r)[1]), "=r"((r)[2]), "=r"((r)[3]) : "r"(a))

#define MMA_BF16(d, a, b0v, b1v) \
    asm volatile("mma.sync.aligned.m16n8k16.row.col.f32.bf16.bf16.f32 " \
                 "{%0,%1,%2,%3}, {%4,%5,%6,%7}, {%8,%9}, {%0,%1,%2,%3};" \
                 : "+f"((d)[0]), "+f"((d)[1]), "+f"((d)[2]), "+f"((d)[3]) \
                 : "r"((a)[0]), "r"((a)[1]), "r"((a)[2]), "r"((a)[3]), "r"(b0v), "r"(b1v))

// ---------------- HMMA GEMM: C[M,Nc] = A[M,256] @ B[Nc,256]^T (bf16x3) ----------------
// A splits [M,256] row-major bf16; B splits [Nc,256] row-major bf16 (K-major).
// 128x128 CTA tile, 256 threads: warp grid 4(m) x 2(n), warp tile 32x64.
#define SM_AHI 1024
#define SM_ALO (1024 + 16384)
#define SM_BHI (1024 + 32768)
#define SM_BLO (1024 + 49152)
#define SC_P 129
#define SM_TOTAL (1024 + 128 * SC_P * 4)  // 67072 (> 1024+65536 mainloop need)
enum { E_STORE = 0, E_SPLITBIAS = 1, E_BIAS = 2, E_LSTM = 3 };

template <int EPI>
__global__ void __launch_bounds__(256, 2)
gemm_mma(const __nv_bfloat16* __restrict__ Ah, const __nv_bfloat16* __restrict__ Al,
         const __nv_bfloat16* __restrict__ Bh, const __nv_bfloat16* __restrict__ Bl,
         int M, int ldc,
         float* __restrict__ C, const float* __restrict__ bias,
         __nv_bfloat16* __restrict__ Oh, __nv_bfloat16* __restrict__ Ol,
         const float* __restrict__ G0, const float* __restrict__ uvp,
         const float* __restrict__ prevv, float* __restrict__ cst)
{
    extern __shared__ char smem[];
    uint32_t sb = smem_u32(smem);
    float* aux = (float*)smem;                  // 128 floats
    float* sC = (float*)(smem + 1024);          // epilogue: 128 x SC_P floats
    int tid = threadIdx.x, lane = tid & 31, wid = tid >> 5;
    int m0 = blockIdx.x * 128, n0 = blockIdx.y * 128;

    if ((EPI == E_SPLITBIAS || EPI == E_BIAS) && tid < 128) aux[tid] = bias[n0 + tid];
    if (EPI == E_LSTM && tid < 128) aux[tid] = uvp[n0 + tid];

    int warp_m = (wid & 3) * 32, warp_n = (wid >> 2) * 64;
    float acc[2][8][4];
#pragma unroll
    for (int i = 0; i < 2; i++)
#pragma unroll
        for (int j = 0; j < 8; j++)
#pragma unroll
            for (int k = 0; k < 4; k++) acc[i][j][k] = 0.f;

    const uint4 zz = make_uint4(0u, 0u, 0u, 0u);
    // ldmatrix lane addressing
    int a_r = lane & 15, a_k = (lane >> 4) * 16;
    int b_r = (lane & 7) | ((lane & 16) >> 1), b_k = ((lane >> 3) & 1) * 16;

#pragma unroll 1
    for (int kc = 0; kc < 4; kc++) {
        __syncthreads();
#pragma unroll
        for (int i = 0; i < 4; i++) {
            int linear = i * 256 + tid;
            int row = linear >> 3, q = linear & 7;
            uint32_t sw = swz(row * 128 + q * 16);
            int gm = m0 + row;
            uint4 vah = zz, val_ = zz;
            if (gm < M) {
                size_t ga = (size_t)gm * 256 + kc * 64 + q * 8;
                vah = *(const uint4*)(Ah + ga);
                val_ = *(const uint4*)(Al + ga);
            }
            *(uint4*)(smem + SM_AHI + sw) = vah;
            *(uint4*)(smem + SM_ALO + sw) = val_;
            size_t gb = (size_t)(n0 + row) * 256 + kc * 64 + q * 8;
            *(uint4*)(smem + SM_BHI + sw) = *(const uint4*)(Bh + gb);
            *(uint4*)(smem + SM_BLO + sw) = *(const uint4*)(Bl + gb);
        }
        __syncthreads();
#pragma unroll 1
        for (int ks = 0; ks < 4; ks++) {
            uint32_t ah0[4], ah1[4], al0[4], al1[4];
            uint32_t ao0 = swz((warp_m + a_r) * 128 + ks * 32 + a_k);
            uint32_t ao1 = swz((warp_m + 16 + a_r) * 128 + ks * 32 + a_k);
            LDSM4(ah0, sb + SM_AHI + ao0);
            LDSM4(ah1, sb + SM_AHI + ao1);
            LDSM4(al0, sb + SM_ALO + ao0);
            LDSM4(al1, sb + SM_ALO + ao1);
#pragma unroll
            for (int ng = 0; ng < 4; ng++) {
                uint32_t bh[4], bl[4];
                uint32_t bo = swz((warp_n + ng * 16 + b_r) * 128 + ks * 32 + b_k);
                LDSM4(bh, sb + SM_BHI + bo);
                LDSM4(bl, sb + SM_BLO + bo);
                float* d00 = acc[0][2 * ng];
                float* d01 = acc[0][2 * ng + 1];
                float* d10 = acc[1][2 * ng];
                float* d11 = acc[1][2 * ng + 1];
                MMA_BF16(d00, ah0, bh[0], bh[1]);
                MMA_BF16(d01, ah0, bh[2], bh[3]);
                MMA_BF16(d10, ah1, bh[0], bh[1]);
                MMA_BF16(d11, ah1, bh[2], bh[3]);
                MMA_BF16(d00, ah0, bl[0], bl[1]);
                MMA_BF16(d01, ah0, bl[2], bl[3]);
                MMA_BF16(d10, ah1, bl[0], bl[1]);
                MMA_BF16(d11, ah1, bl[2], bl[3]);
                MMA_BF16(d00, al0, bh[0], bh[1]);
                MMA_BF16(d01, al0, bh[2], bh[3]);
                MMA_BF16(d10, al1, bh[0], bh[1]);
                MMA_BF16(d11, al1, bh[2], bh[3]);
            }
        }
    }

    // dump fragments to smem (pitch SC_P avoids bank conflicts on row-strided reads)
    __syncthreads();
    {
        int g = lane >> 2, ci = (lane & 3) * 2;
#pragma unroll
        for (int mt = 0; mt < 2; mt++)
#pragma unroll
            for (int nt = 0; nt < 8; nt++) {
                int row = warp_m + mt * 16 + g;
                int col = warp_n + nt * 8 + ci;
                sC[row * SC_P + col] = acc[mt][nt][0];
                sC[row * SC_P + col + 1] = acc[mt][nt][1];
                sC[(row + 8) * SC_P + col] = acc[mt][nt][2];
                sC[(row + 8) * SC_P + col + 1] = acc[mt][nt][3];
            }
    }
    __syncthreads();

    // epilogue: 2 threads per row, each handles 2 chunks of 32 cols
    int row = tid & 127, half = tid >> 7;
    int m = m0 + row;
    bool act = m < M;
    float pv = 0.f;
    if (EPI == E_LSTM && act) pv = prevv[m];

#pragma unroll 1
    for (int qq = 0; qq < 2; qq++) {
        int q = half * 2 + qq;
        if (!act) continue;
        float r[32];
#pragma unroll
        for (int i = 0; i < 32; i++) r[i] = sC[row * SC_P + q * 32 + i];

        if (EPI == E_STORE || EPI == E_BIAS) {
            float* cp = C + (size_t)m * ldc + n0 + q * 32;
#pragma unroll
            for (int i = 0; i < 8; i++) {
                float4 v;
                v.x = r[4 * i + 0];
                v.y = r[4 * i + 1];
                v.z = r[4 * i + 2];
                v.w = r[4 * i + 3];
                if (EPI == E_BIAS) {
                    v.x += aux[q * 32 + 4 * i + 0];
                    v.y += aux[q * 32 + 4 * i + 1];
                    v.z += aux[q * 32 + 4 * i + 2];
                    v.w += aux[q * 32 + 4 * i + 3];
                }
                *(float4*)(cp + i * 4) = v;
            }
        } else if (EPI == E_SPLITBIAS) {
            unsigned short hs[32], ls[32];
#pragma unroll
            for (int i = 0; i < 32; i++) {
                float v = r[i] + aux[q * 32 + i];
                splitf(v, hs[i], ls[i]);
            }
            size_t ob = (size_t)m * 256 + n0 + q * 32;
#pragma unroll
            for (int b = 0; b < 4; b++) {
                uint4 uh, ul;
                uh.x = pk16(hs[8 * b + 0], hs[8 * b + 1]); uh.y = pk16(hs[8 * b + 2], hs[8 * b + 3]);
                uh.z = pk16(hs[8 * b + 4], hs[8 * b + 5]); uh.w = pk16(hs[8 * b + 6], hs[8 * b + 7]);
                ul.x = pk16(ls[8 * b + 0], ls[8 * b + 1]); ul.y = pk16(ls[8 * b + 2], ls[8 * b + 3]);
                ul.z = pk16(ls[8 * b + 4], ls[8 * b + 5]); ul.w = pk16(ls[8 * b + 6], ls[8 * b + 7]);
                *(uint4*)(Oh + ob + b * 8) = uh;
                *(uint4*)(Ol + ob + b * 8) = ul;
            }
        } else {  // E_LSTM
            float g0v[32];
            const float* gp = G0 + (size_t)m * ldc + n0 + q * 32;
#pragma unroll
            for (int i = 0; i < 8; i++) {
                float4 t = *(const float4*)(gp + i * 4);
                g0v[4 * i] = t.x; g0v[4 * i + 1] = t.y; g0v[4 * i + 2] = t.z; g0v[4 * i + 3] = t.w;
            }
            int jb = (n0 + q * 32) >> 2;
            float c8[8];
            {
                float4 c0 = *(const float4*)(cst + (size_t)m * 256 + jb);
                float4 c1 = *(const float4*)(cst + (size_t)m * 256 + jb + 4);
                c8[0] = c0.x; c8[1] = c0.y; c8[2] = c0.z; c8[3] = c0.w;
                c8[4] = c1.x; c8[5] = c1.y; c8[6] = c1.z; c8[7] = c1.w;
            }
            unsigned short hh[8], hl[8];
#pragma unroll
            for (int f = 0; f < 8; f++) {
                int b = 4 * f;
                float ig = sigm(r[b + 0] + g0v[b + 0] + pv * aux[q * 32 + b + 0]);
                float fg = sigm(r[b + 1] + g0v[b + 1] + pv * aux[q * 32 + b + 1]);
                float gg = tanhf(r[b + 2] + g0v[b + 2] + pv * aux[q * 32 + b + 2]);
                float og = sigm(r[b + 3] + g0v[b + 3] + pv * aux[q * 32 + b + 3]);
                float cn = fg * c8[f] + ig * gg;
                c8[f] = cn;
                float hv = og * tanhf(cn);
                splitf(hv, hh[f], hl[f]);
            }
            {
                float4 c0 = make_float4(c8[0], c8[1], c8[2], c8[3]);
                float4 c1 = make_float4(c8[4], c8[5], c8[6], c8[7]);
                *(float4*)(cst + (size_t)m * 256 + jb) = c0;
                *(float4*)(cst + (size_t)m * 256 + jb + 4) = c1;
            }
            uint4 uh, ul;
            uh.x = pk16(hh[0], hh[1]); uh.y = pk16(hh[2], hh[3]);
            uh.z = pk16(hh[4], hh[5]); uh.w = pk16(hh[6], hh[7]);
            ul.x = pk16(hl[0], hl[1]); ul.y = pk16(hl[2], hl[3]);
            ul.z = pk16(hl[4], hl[5]); ul.w = pk16(hl[6], hl[7]);
            *(uint4*)(Oh + (size_t)m * 256 + jb) = uh;
            *(uint4*)(Ol + (size_t)m * 256 + jb) = ul;
        }
    }
}

// ---------------- CSR build ----------------
__global__ void zero_i_k(int* p, int n) {
    int i = blockIdx.x * 256 + threadIdx.x;
    if (i < n) p[i] = 0;
}
__global__ void zero_f_k(float* p, int n) {
    int i = blockIdx.x * 256 + threadIdx.x;
    if (i < n) p[i] = 0.f;
}
__global__ void count_k(const int* __restrict__ dst, int* __restrict__ deg, int E) {
    int e = blockIdx.x * 256 + threadIdx.x;
    if (e < E) atomicAdd(&deg[dst[e]], 1);
}
__global__ void scan_k(const int* __restrict__ deg, int* __restrict__ off, int* __restrict__ cur, int n) {
    __shared__ int s[1024];
    int t = threadIdx.x;
    int per = (n + 1023) >> 10;
    int b = t * per;
    int e = min(b + per, n);
    int sum = 0;
    for (int i = b; i < e; i++) sum += deg[i];
    s[t] = sum;
    __syncthreads();
    for (int d = 1; d < 1024; d <<= 1) {
        int v = (t >= d) ? s[t - d] : 0;
        __syncthreads();
        s[t] += v;
        __syncthreads();
    }
    int run = s[t] - sum;
    for (int i = b; i < e; i++) { off[i] = run; cur[i] = run; run += deg[i]; }
    if (t == 1023) off[n] = s[1023];
}
__global__ void scatter_k(const int* __restrict__ dst, int* __restrict__ cur, int* __restrict__ eidx, int E) {
    int e = blockIdx.x * 256 + threadIdx.x;
    if (e < E) {
        int p = atomicAdd(&cur[dst[e]], 1);
        eidx[p] = e;
    }
}

// ---------------- weight prep ----------------
__global__ void wsT_k(const float* __restrict__ w, __nv_bfloat16* __restrict__ oh,
                      __nv_bfloat16* __restrict__ ol) {
    int n = blockIdx.x, k = threadIdx.x;
    float v = w[k * 256 + n];
    unsigned short h, l;
    splitf(v, h, l);
    oh[n * 256 + k] = __ushort_as_bfloat16(h);
    ol[n * 256 + k] = __ushort_as_bfloat16(l);
}
__global__ void mlpb_k(const float* __restrict__ mw, __nv_bfloat16* __restrict__ oh,
                       __nv_bfloat16* __restrict__ ol) {
    int n = blockIdx.x, k = threadIdx.x;
    float v = mw[n * 257 + 1 + k];
    unsigned short h, l;
    splitf(v, h, l);
    oh[n * 256 + k] = __ushort_as_bfloat16(h);
    ol[n * 256 + k] = __ushort_as_bfloat16(l);
}
__global__ void wperm_k(const float* __restrict__ w, __nv_bfloat16* __restrict__ oh,
                        __nv_bfloat16* __restrict__ ol) {
    int pg = blockIdx.x, k = threadIdx.x;
    int row = (pg & 3) * 256 + (pg >> 2);
    float v = w[(size_t)row * 256 + k];
    unsigned short h, l;
    splitf(v, h, l);
    oh[(size_t)pg * 256 + k] = __ushort_as_bfloat16(h);
    ol[(size_t)pg * 256 + k] = __ushort_as_bfloat16(l);
}
__global__ void uvec2_k(const float* __restrict__ wih, const float* __restrict__ mw,
                        const float* __restrict__ bih, const float* __restrict__ bhh,
                        float* __restrict__ up, float* __restrict__ bsp) {
    int pg = blockIdx.x * 256 + threadIdx.x;
    int row = (pg & 3) * 256 + (pg >> 2);
    float s = 0.f;
    for (int k = 0; k < 256; k++) s += wih[(size_t)row * 256 + k] * mw[k * 257];
    up[pg] = s;
    bsp[pg] = bih[row] + bhh[row];
}
__global__ void xsplit_k(const float* __restrict__ x, __nv_bfloat16* __restrict__ oh,
                         __nv_bfloat16* __restrict__ ol, int n) {
    int i = blockIdx.x * 256 + threadIdx.x;
    if (i >= n) return;
    unsigned short h, l;
    splitf(x[i], h, l);
    oh[i] = __ushort_as_bfloat16(h);
    ol[i] = __ushort_as_bfloat16(l);
}

// ---------------- GAT edge kernels ----------------
__device__ __forceinline__ float lreluf(float v) { return v > 0.f ? v : 0.2f * v; }
__device__ __forceinline__ float eluf(float v) { return v > 0.f ? v : expm1f(v); }

__global__ void edge_logits_k(const float* __restrict__ xl, const float* __restrict__ xr,
                              const int* __restrict__ src, const int* __restrict__ dst,
                              const float* __restrict__ att, float* __restrict__ elog, int E) {
    __shared__ float satt[HID];
    int tid = threadIdx.x;
    satt[tid] = att[tid];
    __syncthreads();
    int lane = tid & 31, w = tid >> 5;
    int e = blockIdx.x * 8 + w;
    if (e >= E) return;
    int s = src[e], d = dst[e];
    const float4* pa = (const float4*)(xl + (size_t)s * HID + lane * 8);
    const float4* pb = (const float4*)(xr + (size_t)d * HID + lane * 8);
    float4 a0 = pa[0], a1 = pa[1], b0 = pb[0], b1 = pb[1];
    const float* at = satt + lane * 8;
    float p = 0.f;
    p += at[0] * lreluf(a0.x + b0.x);
    p += at[1] * lreluf(a0.y + b0.y);
    p += at[2] * lreluf(a0.z + b0.z);
    p += at[3] * lreluf(a0.w + b0.w);
    p += at[4] * lreluf(a1.x + b1.x);
    p += at[5] * lreluf(a1.y + b1.y);
    p += at[6] * lreluf(a1.z + b1.z);
    p += at[7] * lreluf(a1.w + b1.w);
    p += __shfl_xor_sync(0xffffffffu, p, 1);
    p += __shfl_xor_sync(0xffffffffu, p, 2);
    p += __shfl_xor_sync(0xffffffffu, p, 4);
    if ((lane & 7) == 0) elog[(size_t)e * NH + (lane >> 3)] = expf(p);
}

__global__ void aggregate_k(const float* __restrict__ xl, const float* __restrict__ elog,
                            const int* __restrict__ src,
                            const int* __restrict__ off, const int* __restrict__ eidx,
                            const float* __restrict__ bias,
                            __nv_bfloat16* __restrict__ oh, __nv_bfloat16* __restrict__ ol, int N) {
    int tid = threadIdx.x;
    int lane = tid & 31, w = tid >> 5;
    int n = blockIdx.x * 8 + w;
    if (n >= N) return;
    int beg = off[n], end = off[n + 1];
    int h = lane >> 3;
    float den = 0.f;
    for (int j = beg; j < end; j++) den += elog[(size_t)eidx[j] * NH + h];
    float rin = 1.f / den;
    float a[8];
#pragma unroll
    for (int i = 0; i < 8; i++) a[i] = 0.f;
    for (int j = beg; j < end; j++) {
        int e = eidx[j];
        float wg = elog[(size_t)e * NH + h] * rin;
        const float4* pv = (const float4*)(xl + (size_t)src[e] * HID + lane * 8);
        float4 v0 = pv[0], v1 = pv[1];
        a[0] += wg * v0.x; a[1] += wg * v0.y; a[2] += wg * v0.z; a[3] += wg * v0.w;
        a[4] += wg * v1.x; a[5] += wg * v1.y; a[6] += wg * v1.z; a[7] += wg * v1.w;
    }
    const float* bb = bias + lane * 8;
    unsigned short hs[8], ls[8];
#pragma unroll
    for (int i = 0; i < 8; i++) {
        float v = eluf(a[i] + bb[i]);
        splitf(v, hs[i], ls[i]);
    }
    size_t ob = (size_t)n * HID + lane * 8;
    uint4 uh, ul;
    uh.x = pk16(hs[0], hs[1]); uh.y = pk16(hs[2], hs[3]);
    uh.z = pk16(hs[4], hs[5]); uh.w = pk16(hs[6], hs[7]);
    ul.x = pk16(ls[0], ls[1]); ul.y = pk16(ls[2], ls[3]);
    ul.z = pk16(ls[4], ls[5]); ul.w = pk16(ls[6], ls[7]);
    *(uint4*)(oh + ob) = uh;
    *(uint4*)(ol + ob) = ul;
}

// ---------------- decoder small kernels ----------------
__global__ void rowdot2_k(const __nv_bfloat16* __restrict__ hi, const __nv_bfloat16* __restrict__ lo,
                          const float* __restrict__ w, const float* __restrict__ b,
                          float* __restrict__ prev, float* __restrict__ outp, int step, int N) {
    int wid = blockIdx.x * 8 + (threadIdx.x >> 5);
    int lane = threadIdx.x & 31;
    if (wid >= N) return;
    size_t base = (size_t)wid * HID;
    float s = 0.f;
#pragma unroll
    for (int i = 0; i < 8; i++) {
        int k = lane + i * 32;
        s += (__bfloat162float(hi[base + k]) + __bfloat162float(lo[base + k])) * w[k];
    }
    for (int d = 16; d; d >>= 1) s += __shfl_xor_sync(0xffffffffu, s, d);
    if (lane == 0) {
        float t = s + b[0];
        prev[wid] = t;
        if (outp) outp[(size_t)wid * TOUT + step] = t;
    }
}

// ---------------- launch ----------------
extern "C" void kernel_launch(void* const* d_in, const int* in_sizes, int n_in,
                              void* d_out, int out_size) {
    const float* x     = (const float*)d_in[0];
    const int*   ei    = (const int*)d_in[1];
    const float* w_src = (const float*)d_in[2];
    const float* w_dst = (const float*)d_in[3];
    const float* att   = (const float*)d_in[4];
    const float* gbias = (const float*)d_in[5];
    const float* mlp_w = (const float*)d_in[6];
    const float* mlp_b = (const float*)d_in[7];
    const float* wih   = (const float*)d_in[8];
    const float* whh   = (const float*)d_in[9];
    const float* bih   = (const float*)d_in[10];
    const float* bhh   = (const float*)d_in[11];
    const float* initw = (const float*)d_in[12];
    const float* initb = (const float*)d_in[13];
    const float* outw  = (const float*)d_in[14];
    const float* outb  = (const float*)d_in[15];
    float* out = (float*)d_out;

    int N = in_sizes[0] / HID;
    int E = in_sizes[1] / 2;

    float *xl, *xr, *elog, *G0, *cst, *prev, *up, *bsp;
    int *deg, *off, *cur, *eidx;
    __nv_bfloat16 *s0h, *s0l, *hAh, *hAl, *hBh, *hBl, *csh, *csl;
    __nv_bfloat16 *wgh, *wgl, *mbh, *mbl, *wihh, *wihl, *whhh, *whhl;
    cudaGetSymbolAddress((void**)&xl, g_xl);
    cudaGetSymbolAddress((void**)&xr, g_xr);
    cudaGetSymbolAddress((void**)&elog, g_elog);
    cudaGetSymbolAddress((void**)&G0, g_G0);
    cudaGetSymbolAddress((void**)&cst, g_c);
    cudaGetSymbolAddress((void**)&prev, g_prev);
    cudaGetSymbolAddress((void**)&up, g_up);
    cudaGetSymbolAddress((void**)&bsp, g_bsp);
    cudaGetSymbolAddress((void**)&deg, g_deg);
    cudaGetSymbolAddress((void**)&off, g_off);
    cudaGetSymbolAddress((void**)&cur, g_cur);
    cudaGetSymbolAddress((void**)&eidx, g_eidx);
    cudaGetSymbolAddress((void**)&s0h, g_s0h);
    cudaGetSymbolAddress((void**)&s0l, g_s0l);
    cudaGetSymbolAddress((void**)&hAh, g_hAh);
    cudaGetSymbolAddress((void**)&hAl, g_hAl);
    cudaGetSymbolAddress((void**)&hBh, g_hBh);
    cudaGetSymbolAddress((void**)&hBl, g_hBl);
    cudaGetSymbolAddress((void**)&csh, g_csh);
    cudaGetSymbolAddress((void**)&csl, g_csl);
    cudaGetSymbolAddress((void**)&wgh, g_wgh);
    cudaGetSymbolAddress((void**)&wgl, g_wgl);
    cudaGetSymbolAddress((void**)&mbh, g_mbh);
    cudaGetSymbolAddress((void**)&mbl, g_mbl);
    cudaGetSymbolAddress((void**)&wihh, g_wihh);
    cudaGetSymbolAddress((void**)&wihl, g_wihl);
    cudaGetSymbolAddress((void**)&whhh, g_whhh);
    cudaGetSymbolAddress((void**)&whhl, g_whhl);

    cudaFuncSetAttribute(gemm_mma<E_STORE>, cudaFuncAttributeMaxDynamicSharedMemorySize, SM_TOTAL);
    cudaFuncSetAttribute(gemm_mma<E_SPLITBIAS>, cudaFuncAttributeMaxDynamicSharedMemorySize, SM_TOTAL);
    cudaFuncSetAttribute(gemm_mma<E_BIAS>, cudaFuncAttributeMaxDynamicSharedMemorySize, SM_TOTAL);
    cudaFuncSetAttribute(gemm_mma<E_LSTM>, cudaFuncAttributeMaxDynamicSharedMemorySize, SM_TOTAL);

    int eb = (E + 255) / 256;
    int nb = (N + 255) / 256;

    // CSR by destination
    zero_i_k<<<nb, 256>>>(deg, N);
    count_k<<<eb, 256>>>(ei + E, deg, E);
    scan_k<<<1, 1024>>>(deg, off, cur, N);
    scatter_k<<<eb, 256>>>(ei + E, cur, eidx, E);

    // weight prep
    for (int l = 0; l < NL; l++) {
        wsT_k<<<256, 256>>>(w_src + (size_t)l * 65536, wgh + (size_t)(2 * l) * 65536, wgl + (size_t)(2 * l) * 65536);
        wsT_k<<<256, 256>>>(w_dst + (size_t)l * 65536, wgh + (size_t)(2 * l + 1) * 65536, wgl + (size_t)(2 * l + 1) * 65536);
    }
    mlpb_k<<<256, 256>>>(mlp_w, mbh, mbl);
    wperm_k<<<1024, 256>>>(wih, wihh, wihl);
    wperm_k<<<1024, 256>>>(whh, whhh, whhl);
    uvec2_k<<<4, 256>>>(wih, mlp_w, bih, bhh, up, bsp);
    xsplit_k<<<(N * HID + 255) / 256, 256>>>(x, s0h, s0l, N * HID);
    zero_f_k<<<(N * HID + 255) / 256, 256>>>(cst, N * HID);

    int mg = (N + 127) / 128;
    int egrid = (E + 7) / 8;
    int ngrid = (N + 7) / 8;

    // GAT layers (HMMA GEMMs for projections)
    __nv_bfloat16 *sh = s0h, *sl = s0l;
    for (int l = 0; l < NL; l++) {
        gemm_mma<E_STORE><<<dim3(mg, 2), 256, SM_TOTAL>>>(
            sh, sl, wgh + (size_t)(2 * l) * 65536, wgl + (size_t)(2 * l) * 65536,
            N, HID, xl, nullptr, nullptr, nullptr, nullptr, nullptr, nullptr, nullptr);
        gemm_mma<E_STORE><<<dim3(mg, 2), 256, SM_TOTAL>>>(
            sh, sl, wgh + (size_t)(2 * l + 1) * 65536, wgl + (size_t)(2 * l + 1) * 65536,
            N, HID, xr, nullptr, nullptr, nullptr, nullptr, nullptr, nullptr, nullptr);
        edge_logits_k<<<egrid, 256>>>(xl, xr, ei, ei + E, att + l * HID, elog, E);
        __nv_bfloat16* doh = (l == 0) ? s0h : hAh;
        __nv_bfloat16* dol = (l == 0) ? s0l : hAl;
        aggregate_k<<<ngrid, 256>>>(xl, elog, ei, off, eidx, gbias + l * HID, doh, dol, N);
        sh = doh; sl = dol;
    }
    // sh/sl == hAh/hAl == h0 splits

    // decoder precompute: cm = h0 @ mlp(1:)^T + mlp_b  (as splits)
    gemm_mma<E_SPLITBIAS><<<dim3(mg, 2), 256, SM_TOTAL>>>(
        hAh, hAl, mbh, mbl, N, HID, nullptr, mlp_b, csh, csl, nullptr, nullptr, nullptr, nullptr);
    // G0p = cm @ WihP^T + (bih+bhh) permuted
    gemm_mma<E_BIAS><<<dim3(mg, 8), 256, SM_TOTAL>>>(
        csh, csl, wihh, wihl, N, 1024, G0, bsp, nullptr, nullptr, nullptr, nullptr, nullptr, nullptr);
    rowdot2_k<<<ngrid, 256>>>(hAh, hAl, initw, initb, prev, nullptr, 0, N);

    // recurrent steps: h ping-pongs A <-> B
    for (int s = 0; s < TOUT; s++) {
        __nv_bfloat16 *inh = (s & 1) ? hBh : hAh, *inl = (s & 1) ? hBl : hAl;
        __nv_bfloat16 *oh = (s & 1) ? hAh : hBh, *ol = (s & 1) ? hAl : hBl;
        gemm_mma<E_LSTM><<<dim3(mg, 8), 256, SM_TOTAL>>>(
            inh, inl, whhh, whhl, N, 1024, nullptr, nullptr, oh, ol, G0, up, prev, cst);
        rowdot2_k<<<ngrid, 256>>>(oh, ol, outw, outb, prev, out, s, N);
    }
}

// round 10
// speedup vs baseline: 2.4989x; 1.2795x over previous
#include <cuda_runtime.h>
#include <cuda_fp16.h>
#include <math.h>
#include <stdint.h>

#define HID 256
#define NH 4
#define NL 2
#define TOUT 12
#define MAXN 24000
#define MAXE 400000

// ---------------- scratch (static device globals; no allocation) ----------------
__device__ __half g_xl[MAXN * HID];
__device__ __half g_xr[MAXN * HID];
__device__ float g_elog[MAXE * NH];
__device__ int   g_deg[MAXN];
__device__ int   g_off[MAXN + 1];
__device__ int   g_cur[MAXN];
__device__ int   g_eidx[MAXE];
__device__ __half g_G0[(size_t)MAXN * 1024];
__device__ float g_c[MAXN * HID];
__device__ float g_prev[MAXN];
__device__ float g_up[1024];
__device__ float g_bsp[1024];

// fp16 activation buffers (single precision-rounded)
__device__ __half g_s0[MAXN * HID];
__device__ __half g_hA[MAXN * HID];
__device__ __half g_hB[MAXN * HID];
__device__ __half g_cs[MAXN * HID];
// fp16 weight splits (hi + lo)
__device__ __half g_wgh[4 * 256 * 256];
__device__ __half g_wgl[4 * 256 * 256];
__device__ __half g_mbh[256 * 256];
__device__ __half g_mbl[256 * 256];
__device__ __half g_wihh[1024 * 256];
__device__ __half g_wihl[1024 * 256];
__device__ __half g_whhh[1024 * 256];
__device__ __half g_whhl[1024 * 256];

// ---------------- helpers ----------------
__device__ __forceinline__ uint32_t smem_u32(const void* p) {
    uint32_t a;
    asm("{ .reg .u64 t; cvta.to.shared.u64 t, %1; cvt.u32.u64 %0, t; }" : "=r"(a) : "l"(p));
    return a;
}
__device__ __forceinline__ uint32_t swz(uint32_t b) { return b ^ ((b >> 3) & 0x70); }

__device__ __forceinline__ void splith(float v, __half& h, __half& l) {
    h = __float2half_rn(v);
    l = __float2half_rn(v - __half2float(h));
}
__device__ __forceinline__ float sigm(float x) { return 1.f / (1.f + expf(-x)); }

#define LDSM4(r, a) \
    asm volatile("ldmatrix.sync.aligned.m8n8.x4.shared.b16 {%0,%1,%2,%3}, [%4];" \
                 : "=r"((r)[0]), "=r"((r)[1]), "=r"((r)[2]), "=r"((r)[3]) : "r"(a))

#define MMA_F16(d, a, b0v, b1v) \
    asm volatile("mma.sync.aligned.m16n8k16.row.col.f32.f16.f16.f32 " \
                 "{%0,%1,%2,%3}, {%4,%5,%6,%7}, {%8,%9}, {%0,%1,%2,%3};" \
                 : "+f"((d)[0]), "+f"((d)[1]), "+f"((d)[2]), "+f"((d)[3]) \
                 : "r"((a)[0]), "r"((a)[1]), "r"((a)[2]), "r"((a)[3]), "r"(b0v), "r"(b1v))

// ---------------- HMMA GEMM: C[M,Nc] = A[M,256] @ (Wh+Wl)[Nc,256]^T (fp16 2-term) ----------------
// A fp16 [M,256] row-major; Wh/Wl fp16 [Nc,256] row-major (K-major).
// 128x128 CTA tile, 256 threads: warp grid 4(m) x 2(n), warp tile 32x64.
#define SM_A  1024
#define SM_BH (1024 + 16384)
#define SM_BL (1024 + 32768)
#define SC_P 129
#define SM_TOTAL (1024 + 128 * SC_P * 4)  // 67072 (mainloop needs 1024+49152)
enum { E_STOREH = 0, E_BIASH = 1, E_LSTM = 2 };

template <int EPI>
__global__ void __launch_bounds__(256, 2)
gemm_mma(const __half* __restrict__ A,
         const __half* __restrict__ Bh, const __half* __restrict__ Bl,
         int M, int ldc,
         const float* __restrict__ bias,
         __half* __restrict__ Oh,
         const __half* __restrict__ G0, const float* __restrict__ uvp,
         const float* __restrict__ prevv, float* __restrict__ cst)
{
    extern __shared__ char smem[];
    uint32_t sb = smem_u32(smem);
    float* aux = (float*)smem;                  // 128 floats
    float* sC = (float*)(smem + 1024);          // epilogue: 128 x SC_P floats
    int tid = threadIdx.x, lane = tid & 31, wid = tid >> 5;
    int m0 = blockIdx.x * 128, n0 = blockIdx.y * 128;

    if (EPI == E_BIASH && tid < 128) aux[tid] = bias[n0 + tid];
    if (EPI == E_LSTM && tid < 128) aux[tid] = uvp[n0 + tid];

    int warp_m = (wid & 3) * 32, warp_n = (wid >> 2) * 64;
    float acc[2][8][4];
#pragma unroll
    for (int i = 0; i < 2; i++)
#pragma unroll
        for (int j = 0; j < 8; j++)
#pragma unroll
            for (int k = 0; k < 4; k++) acc[i][j][k] = 0.f;

    const uint4 zz = make_uint4(0u, 0u, 0u, 0u);
    // ldmatrix lane addressing
    int a_r = lane & 15, a_k = (lane >> 4) * 16;
    int b_r = (lane & 7) | ((lane & 16) >> 1), b_k = ((lane >> 3) & 1) * 16;

#pragma unroll 1
    for (int kc = 0; kc < 4; kc++) {
        __syncthreads();
#pragma unroll
        for (int i = 0; i < 4; i++) {
            int linear = i * 256 + tid;
            int row = linear >> 3, q = linear & 7;
            uint32_t sw = swz(row * 128 + q * 16);
            int gm = m0 + row;
            uint4 va = zz;
            if (gm < M) va = *(const uint4*)(A + (size_t)gm * 256 + kc * 64 + q * 8);
            *(uint4*)(smem + SM_A + sw) = va;
            size_t gb = (size_t)(n0 + row) * 256 + kc * 64 + q * 8;
            *(uint4*)(smem + SM_BH + sw) = *(const uint4*)(Bh + gb);
            *(uint4*)(smem + SM_BL + sw) = *(const uint4*)(Bl + gb);
        }
        __syncthreads();
#pragma unroll 1
        for (int ks = 0; ks < 4; ks++) {
            uint32_t ah0[4], ah1[4];
            uint32_t ao0 = swz((warp_m + a_r) * 128 + ks * 32 + a_k);
            uint32_t ao1 = swz((warp_m + 16 + a_r) * 128 + ks * 32 + a_k);
            LDSM4(ah0, sb + SM_A + ao0);
            LDSM4(ah1, sb + SM_A + ao1);
#pragma unroll
            for (int ng = 0; ng < 4; ng++) {
                uint32_t bh[4], bl[4];
                uint32_t bo = swz((warp_n + ng * 16 + b_r) * 128 + ks * 32 + b_k);
                LDSM4(bh, sb + SM_BH + bo);
                LDSM4(bl, sb + SM_BL + bo);
                float* d00 = acc[0][2 * ng];
                float* d01 = acc[0][2 * ng + 1];
                float* d10 = acc[1][2 * ng];
                float* d11 = acc[1][2 * ng + 1];
                MMA_F16(d00, ah0, bh[0], bh[1]);
                MMA_F16(d01, ah0, bh[2], bh[3]);
                MMA_F16(d10, ah1, bh[0], bh[1]);
                MMA_F16(d11, ah1, bh[2], bh[3]);
                MMA_F16(d00, ah0, bl[0], bl[1]);
                MMA_F16(d01, ah0, bl[2], bl[3]);
                MMA_F16(d10, ah1, bl[0], bl[1]);
                MMA_F16(d11, ah1, bl[2], bl[3]);
            }
        }
    }

    // dump fragments to smem (pitch SC_P avoids bank conflicts on row-strided reads)
    __syncthreads();
    {
        int g = lane >> 2, ci = (lane & 3) * 2;
#pragma unroll
        for (int mt = 0; mt < 2; mt++)
#pragma unroll
            for (int nt = 0; nt < 8; nt++) {
                int row = warp_m + mt * 16 + g;
                int col = warp_n + nt * 8 + ci;
                sC[row * SC_P + col] = acc[mt][nt][0];
                sC[row * SC_P + col + 1] = acc[mt][nt][1];
                sC[(row + 8) * SC_P + col] = acc[mt][nt][2];
                sC[(row + 8) * SC_P + col + 1] = acc[mt][nt][3];
            }
    }
    __syncthreads();

    // epilogue: 2 threads per row, each handles 2 chunks of 32 cols
    int row = tid & 127, half = tid >> 7;
    int m = m0 + row;
    bool act = m < M;
    float pv = 0.f;
    if (EPI == E_LSTM && act) pv = prevv[m];

#pragma unroll 1
    for (int qq = 0; qq < 2; qq++) {
        int q = half * 2 + qq;
        if (!act) continue;
        float r[32];
#pragma unroll
        for (int i = 0; i < 32; i++) r[i] = sC[row * SC_P + q * 32 + i];

        if (EPI == E_STOREH || EPI == E_BIASH) {
            size_t ob = (size_t)m * ldc + n0 + q * 32;
#pragma unroll
            for (int b = 0; b < 4; b++) {
                uint4 uo;
                __half2* op = (__half2*)&uo;
#pragma unroll
                for (int j = 0; j < 4; j++) {
                    float v0 = r[8 * b + 2 * j], v1 = r[8 * b + 2 * j + 1];
                    if (EPI == E_BIASH) {
                        v0 += aux[q * 32 + 8 * b + 2 * j];
                        v1 += aux[q * 32 + 8 * b + 2 * j + 1];
                    }
                    op[j] = __floats2half2_rn(v0, v1);
                }
                *(uint4*)(Oh + ob + b * 8) = uo;
            }
        } else {  // E_LSTM
            float g0v[32];
            const uint4* gp4 = (const uint4*)(G0 + (size_t)m * ldc + n0 + q * 32);
#pragma unroll
            for (int i = 0; i < 4; i++) {
                uint4 t = gp4[i];
                __half2* hp = (__half2*)&t;
#pragma unroll
                for (int j = 0; j < 4; j++) {
                    float2 f = __half22float2(hp[j]);
                    g0v[8 * i + 2 * j] = f.x;
                    g0v[8 * i + 2 * j + 1] = f.y;
                }
            }
            int jb = (n0 + q * 32) >> 2;
            float c8[8];
            {
                float4 c0 = *(const float4*)(cst + (size_t)m * 256 + jb);
                float4 c1 = *(const float4*)(cst + (size_t)m * 256 + jb + 4);
                c8[0] = c0.x; c8[1] = c0.y; c8[2] = c0.z; c8[3] = c0.w;
                c8[4] = c1.x; c8[5] = c1.y; c8[6] = c1.z; c8[7] = c1.w;
            }
            __half hh[8];
#pragma unroll
            for (int f = 0; f < 8; f++) {
                int b = 4 * f;
                float ig = sigm(r[b + 0] + g0v[b + 0] + pv * aux[q * 32 + b + 0]);
                float fg = sigm(r[b + 1] + g0v[b + 1] + pv * aux[q * 32 + b + 1]);
                float gg = tanhf(r[b + 2] + g0v[b + 2] + pv * aux[q * 32 + b + 2]);
                float og = sigm(r[b + 3] + g0v[b + 3] + pv * aux[q * 32 + b + 3]);
                float cn = fg * c8[f] + ig * gg;
                c8[f] = cn;
                hh[f] = __float2half_rn(og * tanhf(cn));
            }
            {
                float4 c0 = make_float4(c8[0], c8[1], c8[2], c8[3]);
                float4 c1 = make_float4(c8[4], c8[5], c8[6], c8[7]);
                *(float4*)(cst + (size_t)m * 256 + jb) = c0;
                *(float4*)(cst + (size_t)m * 256 + jb + 4) = c1;
            }
            uint4 uo;
            __half2* op = (__half2*)&uo;
            op[0] = __halves2half2(hh[0], hh[1]);
            op[1] = __halves2half2(hh[2], hh[3]);
            op[2] = __halves2half2(hh[4], hh[5]);
            op[3] = __halves2half2(hh[6], hh[7]);
            *(uint4*)(Oh + (size_t)m * 256 + jb) = uo;
        }
    }
}

// ---------------- CSR build ----------------
__global__ void zero_i_k(int* p, int n) {
    int i = blockIdx.x * 256 + threadIdx.x;
    if (i < n) p[i] = 0;
}
__global__ void zero_f_k(float* p, int n) {
    int i = blockIdx.x * 256 + threadIdx.x;
    if (i < n) p[i] = 0.f;
}
__global__ void count_k(const int* __restrict__ dst, int* __restrict__ deg, int E) {
    int e = blockIdx.x * 256 + threadIdx.x;
    if (e < E) atomicAdd(&deg[dst[e]], 1);
}
__global__ void scan_k(const int* __restrict__ deg, int* __restrict__ off, int* __restrict__ cur, int n) {
    __shared__ int s[1024];
    int t = threadIdx.x;
    int per = (n + 1023) >> 10;
    int b = t * per;
    int e = min(b + per, n);
    int sum = 0;
    for (int i = b; i < e; i++) sum += deg[i];
    s[t] = sum;
    __syncthreads();
    for (int d = 1; d < 1024; d <<= 1) {
        int v = (t >= d) ? s[t - d] : 0;
        __syncthreads();
        s[t] += v;
        __syncthreads();
    }
    int run = s[t] - sum;
    for (int i = b; i < e; i++) { off[i] = run; cur[i] = run; run += deg[i]; }
    if (t == 1023) off[n] = s[1023];
}
__global__ void scatter_k(const int* __restrict__ dst, int* __restrict__ cur, int* __restrict__ eidx, int E) {
    int e = blockIdx.x * 256 + threadIdx.x;
    if (e < E) {
        int p = atomicAdd(&cur[dst[e]], 1);
        eidx[p] = e;
    }
}

// ---------------- weight prep ----------------
// transpose-split: out[n*256+k] = splith(w[k*256+n])
__global__ void wsT_k(const float* __restrict__ w, __half* __restrict__ oh,
                      __half* __restrict__ ol) {
    int n = blockIdx.x, k = threadIdx.x;
    __half h, l;
    splith(w[k * 256 + n], h, l);
    oh[n * 256 + k] = h;
    ol[n * 256 + k] = l;
}
__global__ void mlpb_k(const float* __restrict__ mw, __half* __restrict__ oh,
                       __half* __restrict__ ol) {
    int n = blockIdx.x, k = threadIdx.x;
    __half h, l;
    splith(mw[n * 257 + 1 + k], h, l);
    oh[n * 256 + k] = h;
    ol[n * 256 + k] = l;
}
// gate-interleaved permuted split: pg=4j+g -> row g*256+j
__global__ void wperm_k(const float* __restrict__ w, __half* __restrict__ oh,
                        __half* __restrict__ ol) {
    int pg = blockIdx.x, k = threadIdx.x;
    int row = (pg & 3) * 256 + (pg >> 2);
    __half h, l;
    splith(w[(size_t)row * 256 + k], h, l);
    oh[(size_t)pg * 256 + k] = h;
    ol[(size_t)pg * 256 + k] = l;
}
__global__ void uvec2_k(const float* __restrict__ wih, const float* __restrict__ mw,
                        const float* __restrict__ bih, const float* __restrict__ bhh,
                        float* __restrict__ up, float* __restrict__ bsp) {
    int pg = blockIdx.x * 256 + threadIdx.x;
    int row = (pg & 3) * 256 + (pg >> 2);
    float s = 0.f;
    for (int k = 0; k < 256; k++) s += wih[(size_t)row * 256 + k] * mw[k * 257];
    up[pg] = s;
    bsp[pg] = bih[row] + bhh[row];
}
__global__ void xhalf_k(const float* __restrict__ x, __half* __restrict__ o, int n) {
    int i = blockIdx.x * 256 + threadIdx.x;
    if (i < n) o[i] = __float2half_rn(x[i]);
}

// ---------------- GAT edge kernels ----------------
__device__ __forceinline__ float lreluf(float v) { return v > 0.f ? v : 0.2f * v; }
__device__ __forceinline__ float eluf(float v) { return v > 0.f ? v : expm1f(v); }

__global__ void edge_logits_k(const __half* __restrict__ xl, const __half* __restrict__ xr,
                              const int* __restrict__ src, const int* __restrict__ dst,
                              const float* __restrict__ att, float* __restrict__ elog, int E) {
    __shared__ float satt[HID];
    int tid = threadIdx.x;
    satt[tid] = att[tid];
    __syncthreads();
    int lane = tid & 31, w = tid >> 5;
    int e = blockIdx.x * 8 + w;
    if (e >= E) return;
    int s = src[e], d = dst[e];
    uint4 va = *(const uint4*)(xl + (size_t)s * HID + lane * 8);
    uint4 vb = *(const uint4*)(xr + (size_t)d * HID + lane * 8);
    __half2* ha = (__half2*)&va;
    __half2* hb = (__half2*)&vb;
    const float* at = satt + lane * 8;
    float p = 0.f;
#pragma unroll
    for (int j = 0; j < 4; j++) {
        float2 fa = __half22float2(ha[j]);
        float2 fb = __half22float2(hb[j]);
        p += at[2 * j] * lreluf(fa.x + fb.x);
        p += at[2 * j + 1] * lreluf(fa.y + fb.y);
    }
    p += __shfl_xor_sync(0xffffffffu, p, 1);
    p += __shfl_xor_sync(0xffffffffu, p, 2);
    p += __shfl_xor_sync(0xffffffffu, p, 4);
    if ((lane & 7) == 0) elog[(size_t)e * NH + (lane >> 3)] = expf(p);
}

__global__ void aggregate_k(const __half* __restrict__ xl, const float* __restrict__ elog,
                            const int* __restrict__ src,
                            const int* __restrict__ off, const int* __restrict__ eidx,
                            const float* __restrict__ bias,
                            __half* __restrict__ o, int N) {
    int tid = threadIdx.x;
    int lane = tid & 31, w = tid >> 5;
    int n = blockIdx.x * 8 + w;
    if (n >= N) return;
    int beg = off[n], end = off[n + 1];
    int h = lane >> 3;
    float den = 0.f;
    for (int j = beg; j < end; j++) den += elog[(size_t)eidx[j] * NH + h];
    float rin = 1.f / den;
    float a[8];
#pragma unroll
    for (int i = 0; i < 8; i++) a[i] = 0.f;
    for (int j = beg; j < end; j++) {
        int e = eidx[j];
        float wg = elog[(size_t)e * NH + h] * rin;
        uint4 vv = *(const uint4*)(xl + (size_t)src[e] * HID + lane * 8);
        __half2* hv = (__half2*)&vv;
#pragma unroll
        for (int i = 0; i < 4; i++) {
            float2 f = __half22float2(hv[i]);
            a[2 * i] += wg * f.x;
            a[2 * i + 1] += wg * f.y;
        }
    }
    const float* bb = bias + lane * 8;
    uint4 uo;
    __half2* op = (__half2*)&uo;
#pragma unroll
    for (int i = 0; i < 4; i++)
        op[i] = __floats2half2_rn(eluf(a[2 * i] + bb[2 * i]), eluf(a[2 * i + 1] + bb[2 * i + 1]));
    *(uint4*)(o + (size_t)n * HID + lane * 8) = uo;
}

// ---------------- decoder small kernels ----------------
__global__ void rowdot_h(const __half* __restrict__ hi,
                         const float* __restrict__ w, const float* __restrict__ b,
                         float* __restrict__ prev, float* __restrict__ outp, int step, int N) {
    int wid = blockIdx.x * 8 + (threadIdx.x >> 5);
    int lane = threadIdx.x & 31;
    if (wid >= N) return;
    size_t base = (size_t)wid * HID;
    float s = 0.f;
#pragma unroll
    for (int i = 0; i < 8; i++) {
        int k = lane + i * 32;
        s += __half2float(hi[base + k]) * w[k];
    }
    for (int d = 16; d; d >>= 1) s += __shfl_xor_sync(0xffffffffu, s, d);
    if (lane == 0) {
        float t = s + b[0];
        prev[wid] = t;
        if (outp) outp[(size_t)wid * TOUT + step] = t;
    }
}

// ---------------- launch ----------------
extern "C" void kernel_launch(void* const* d_in, const int* in_sizes, int n_in,
                              void* d_out, int out_size) {
    const float* x     = (const float*)d_in[0];
    const int*   ei    = (const int*)d_in[1];
    const float* w_src = (const float*)d_in[2];
    const float* w_dst = (const float*)d_in[3];
    const float* att   = (const float*)d_in[4];
    const float* gbias = (const float*)d_in[5];
    const float* mlp_w = (const float*)d_in[6];
    const float* mlp_b = (const float*)d_in[7];
    const float* wih   = (const float*)d_in[8];
    const float* whh   = (const float*)d_in[9];
    const float* bih   = (const float*)d_in[10];
    const float* bhh   = (const float*)d_in[11];
    const float* initw = (const float*)d_in[12];
    const float* initb = (const float*)d_in[13];
    const float* outw  = (const float*)d_in[14];
    const float* outb  = (const float*)d_in[15];
    float* out = (float*)d_out;

    int N = in_sizes[0] / HID;
    int E = in_sizes[1] / 2;

    float *elog, *cst, *prev, *up, *bsp;
    int *deg, *off, *cur, *eidx;
    __half *xl, *xr, *s0, *hA, *hB, *cs, *G0;
    __half *wgh, *wgl, *mbh, *mbl, *wihh, *wihl, *whhh, *whhl;
    cudaGetSymbolAddress((void**)&xl, g_xl);
    cudaGetSymbolAddress((void**)&xr, g_xr);
    cudaGetSymbolAddress((void**)&elog, g_elog);
    cudaGetSymbolAddress((void**)&G0, g_G0);
    cudaGetSymbolAddress((void**)&cst, g_c);
    cudaGetSymbolAddress((void**)&prev, g_prev);
    cudaGetSymbolAddress((void**)&up, g_up);
    cudaGetSymbolAddress((void**)&bsp, g_bsp);
    cudaGetSymbolAddress((void**)&deg, g_deg);
    cudaGetSymbolAddress((void**)&off, g_off);
    cudaGetSymbolAddress((void**)&cur, g_cur);
    cudaGetSymbolAddress((void**)&eidx, g_eidx);
    cudaGetSymbolAddress((void**)&s0, g_s0);
    cudaGetSymbolAddress((void**)&hA, g_hA);
    cudaGetSymbolAddress((void**)&hB, g_hB);
    cudaGetSymbolAddress((void**)&cs, g_cs);
    cudaGetSymbolAddress((void**)&wgh, g_wgh);
    cudaGetSymbolAddress((void**)&wgl, g_wgl);
    cudaGetSymbolAddress((void**)&mbh, g_mbh);
    cudaGetSymbolAddress((void**)&mbl, g_mbl);
    cudaGetSymbolAddress((void**)&wihh, g_wihh);
    cudaGetSymbolAddress((void**)&wihl, g_wihl);
    cudaGetSymbolAddress((void**)&whhh, g_whhh);
    cudaGetSymbolAddress((void**)&whhl, g_whhl);

    cudaFuncSetAttribute(gemm_mma<E_STOREH>, cudaFuncAttributeMaxDynamicSharedMemorySize, SM_TOTAL);
    cudaFuncSetAttribute(gemm_mma<E_BIASH>, cudaFuncAttributeMaxDynamicSharedMemorySize, SM_TOTAL);
    cudaFuncSetAttribute(gemm_mma<E_LSTM>, cudaFuncAttributeMaxDynamicSharedMemorySize, SM_TOTAL);

    int eb = (E + 255) / 256;
    int nb = (N + 255) / 256;

    // CSR by destination
    zero_i_k<<<nb, 256>>>(deg, N);
    count_k<<<eb, 256>>>(ei + E, deg, E);
    scan_k<<<1, 1024>>>(deg, off, cur, N);
    scatter_k<<<eb, 256>>>(ei + E, cur, eidx, E);

    // weight prep
    for (int l = 0; l < NL; l++) {
        wsT_k<<<256, 256>>>(w_src + (size_t)l * 65536, wgh + (size_t)(2 * l) * 65536, wgl + (size_t)(2 * l) * 65536);
        wsT_k<<<256, 256>>>(w_dst + (size_t)l * 65536, wgh + (size_t)(2 * l + 1) * 65536, wgl + (size_t)(2 * l + 1) * 65536);
    }
    mlpb_k<<<256, 256>>>(mlp_w, mbh, mbl);
    wperm_k<<<1024, 256>>>(wih, wihh, wihl);
    wperm_k<<<1024, 256>>>(whh, whhh, whhl);
    uvec2_k<<<4, 256>>>(wih, mlp_w, bih, bhh, up, bsp);
    xhalf_k<<<(N * HID + 255) / 256, 256>>>(x, s0, N * HID);
    zero_f_k<<<(N * HID + 255) / 256, 256>>>(cst, N * HID);

    int mg = (N + 127) / 128;
    int egrid = (E + 7) / 8;
    int ngrid = (N + 7) / 8;

    // GAT layers (HMMA GEMMs for projections)
    __half* sh = s0;
    for (int l = 0; l < NL; l++) {
        gemm_mma<E_STOREH><<<dim3(mg, 2), 256, SM_TOTAL>>>(
            sh, wgh + (size_t)(2 * l) * 65536, wgl + (size_t)(2 * l) * 65536,
            N, HID, nullptr, xl, nullptr, nullptr, nullptr, nullptr);
        gemm_mma<E_STOREH><<<dim3(mg, 2), 256, SM_TOTAL>>>(
            sh, wgh + (size_t)(2 * l + 1) * 65536, wgl + (size_t)(2 * l + 1) * 65536,
            N, HID, nullptr, xr, nullptr, nullptr, nullptr, nullptr);
        edge_logits_k<<<egrid, 256>>>(xl, xr, ei, ei + E, att + l * HID, elog, E);
        __half* dof = (l == 0) ? s0 : hA;
        aggregate_k<<<ngrid, 256>>>(xl, elog, ei, off, eidx, gbias + l * HID, dof, N);
        sh = dof;
    }
    // sh == hA == h0 (fp16)

    // decoder precompute: cm = h0 @ mlp(1:)^T + mlp_b  (fp16)
    gemm_mma<E_BIASH><<<dim3(mg, 2), 256, SM_TOTAL>>>(
        hA, mbh, mbl, N, HID, mlp_b, cs, nullptr, nullptr, nullptr, nullptr);
    // G0p = cm @ WihP^T + (bih+bhh) permuted  (fp16)
    gemm_mma<E_BIASH><<<dim3(mg, 8), 256, SM_TOTAL>>>(
        cs, wihh, wihl, N, 1024, bsp, G0, nullptr, nullptr, nullptr, nullptr);
    rowdot_h<<<ngrid, 256>>>(hA, initw, initb, prev, nullptr, 0, N);

    // recurrent steps: h ping-pongs A <-> B
    for (int s = 0; s < TOUT; s++) {
        __half* inh = (s & 1) ? hB : hA;
        __half* oh = (s & 1) ? hA : hB;
        gemm_mma<E_LSTM><<<dim3(mg, 8), 256, SM_TOTAL>>>(
            inh, whhh, whhl, N, 1024, nullptr, oh, G0, up, prev, cst);
        rowdot_h<<<ngrid, 256>>>(oh, outw, outb, prev, out, s, N);
    }
}

// round 13
// speedup vs baseline: 3.0752x; 1.2307x over previous
#include <cuda_runtime.h>
#include <cuda_fp16.h>
#include <math.h>
#include <stdint.h>

#define HID 256
#define NH 4
#define NL 2
#define TOUT 12
#define MAXN 24000
#define MAXE 400000

// ---------------- scratch (static device globals; no allocation) ----------------
__device__ __half g_xl[MAXN * HID];
__device__ __half g_xr[MAXN * HID];
__device__ float g_elog[MAXE * NH];
__device__ int   g_deg[MAXN];
__device__ int   g_off[MAXN + 1];
__device__ int   g_cur[MAXN];
__device__ int   g_eidx[MAXE];
__device__ __half g_G0[(size_t)MAXN * 1024];
__device__ float g_c[MAXN * HID];
__device__ float g_prev[MAXN];
__device__ float g_up[1024];
__device__ float g_bsp[1024];

// fp16 activation buffers
__device__ __half g_s0[MAXN * HID];
__device__ __half g_hA[MAXN * HID];
__device__ __half g_hB[MAXN * HID];
__device__ __half g_cs[MAXN * HID];
// fp16 weights (single-term)
__device__ __half g_wg[4 * 256 * 256];
__device__ __half g_mb[256 * 256];
__device__ __half g_wih[1024 * 256];
__device__ __half g_whh[1024 * 256];

// ---------------- helpers ----------------
__device__ __forceinline__ uint32_t smem_u32(const void* p) {
    uint32_t a;
    asm("{ .reg .u64 t; cvta.to.shared.u64 t, %1; cvt.u32.u64 %0, t; }" : "=r"(a) : "l"(p));
    return a;
}
__device__ __forceinline__ uint32_t swz(uint32_t b) { return b ^ ((b >> 3) & 0x70); }
__device__ __forceinline__ float sigm(float x) { return 1.f / (1.f + expf(-x)); }

#define LDSM4(r, a) \
    asm volatile("ldmatrix.sync.aligned.m8n8.x4.shared.b16 {%0,%1,%2,%3}, [%4];" \
                 : "=r"((r)[0]), "=r"((r)[1]), "=r"((r)[2]), "=r"((r)[3]) : "r"(a))

#define MMA_F16(d, a, b0v, b1v) \
    asm volatile("mma.sync.aligned.m16n8k16.row.col.f32.f16.f16.f32 " \
                 "{%0,%1,%2,%3}, {%4,%5,%6,%7}, {%8,%9}, {%0,%1,%2,%3};" \
                 : "+f"((d)[0]), "+f"((d)[1]), "+f"((d)[2]), "+f"((d)[3]) \
                 : "r"((a)[0]), "r"((a)[1]), "r"((a)[2]), "r"((a)[3]), "r"(b0v), "r"(b1v))

// ---------------- HMMA GEMM: C[M,Nc] = A[M,256] @ W[Nc,256]^T (fp16 single-term) ----------------
// Synchronous loader (R10-proven structure). 128x128 CTA tile, 256 threads:
// warp grid 4(m) x 2(n), warp tile 32x64.
#define SM_A  1024
#define SM_B  (1024 + 16384)
#define SC_P 129
#define SM_TOTAL (1024 + 128 * SC_P * 4)  // 67072 (mainloop needs 1024 + 32768)
enum { E_STOREH = 0, E_BIASH = 1, E_LSTM = 2 };

template <int EPI>
__global__ void __launch_bounds__(256, 2)
gemm_mma(const __half* __restrict__ A, const __half* __restrict__ B,
         int M, int ldc,
         const float* __restrict__ bias,
         __half* __restrict__ Oh,
         const __half* __restrict__ G0, const float* __restrict__ uvp,
         const float* __restrict__ prevv, float* __restrict__ cst)
{
    extern __shared__ char smem[];
    uint32_t sb = smem_u32(smem);
    float* aux = (float*)smem;                  // 128 floats
    float* sC = (float*)(smem + 1024);          // epilogue: 128 x SC_P floats
    int tid = threadIdx.x, lane = tid & 31, wid = tid >> 5;
    int m0 = blockIdx.x * 128, n0 = blockIdx.y * 128;

    if (EPI == E_BIASH && tid < 128) aux[tid] = bias[n0 + tid];
    if (EPI == E_LSTM && tid < 128) aux[tid] = uvp[n0 + tid];

    int warp_m = (wid & 3) * 32, warp_n = (wid >> 2) * 64;
    float acc[2][8][4];
#pragma unroll
    for (int i = 0; i < 2; i++)
#pragma unroll
        for (int j = 0; j < 8; j++)
#pragma unroll
            for (int k = 0; k < 4; k++) acc[i][j][k] = 0.f;

    const uint4 zz = make_uint4(0u, 0u, 0u, 0u);
    // ldmatrix lane addressing
    int a_r = lane & 15, a_k = (lane >> 4) * 16;
    int b_r = (lane & 7) | ((lane & 16) >> 1), b_k = ((lane >> 3) & 1) * 16;

#pragma unroll 1
    for (int kc = 0; kc < 4; kc++) {
        __syncthreads();
#pragma unroll
        for (int i = 0; i < 2; i++) {
            int linear = i * 256 + tid;
            int row = linear >> 3, q = linear & 7;
            // two row-phases per region: rows [0,64) then [64,128)
#pragma unroll
            for (int p = 0; p < 2; p++) {
                int rr = row + p * 64;
                uint32_t sw = swz(rr * 128 + q * 16);
                int gm = m0 + rr;
                uint4 va = zz;
                if (gm < M) va = *(const uint4*)(A + (size_t)gm * 256 + kc * 64 + q * 8);
                *(uint4*)(smem + SM_A + sw) = va;
                size_t gb = (size_t)(n0 + rr) * 256 + kc * 64 + q * 8;
                *(uint4*)(smem + SM_B + sw) = *(const uint4*)(B + gb);
            }
        }
        __syncthreads();
#pragma unroll 1
        for (int ks = 0; ks < 4; ks++) {
            uint32_t a0[4], a1[4];
            LDSM4(a0, sb + SM_A + swz((warp_m + a_r) * 128 + ks * 32 + a_k));
            LDSM4(a1, sb + SM_A + swz((warp_m + 16 + a_r) * 128 + ks * 32 + a_k));
#pragma unroll
            for (int ng = 0; ng < 4; ng++) {
                uint32_t b[4];
                LDSM4(b, sb + SM_B + swz((warp_n + ng * 16 + b_r) * 128 + ks * 32 + b_k));
                MMA_F16(acc[0][2 * ng], a0, b[0], b[1]);
                MMA_F16(acc[0][2 * ng + 1], a0, b[2], b[3]);
                MMA_F16(acc[1][2 * ng], a1, b[0], b[1]);
                MMA_F16(acc[1][2 * ng + 1], a1, b[2], b[3]);
            }
        }
    }

    // dump fragments to smem (pitch SC_P avoids bank conflicts on row-strided reads)
    __syncthreads();
    {
        int g = lane >> 2, ci = (lane & 3) * 2;
#pragma unroll
        for (int mt = 0; mt < 2; mt++)
#pragma unroll
            for (int nt = 0; nt < 8; nt++) {
                int row = warp_m + mt * 16 + g;
                int col = warp_n + nt * 8 + ci;
                sC[row * SC_P + col] = acc[mt][nt][0];
                sC[row * SC_P + col + 1] = acc[mt][nt][1];
                sC[(row + 8) * SC_P + col] = acc[mt][nt][2];
                sC[(row + 8) * SC_P + col + 1] = acc[mt][nt][3];
            }
    }
    __syncthreads();

    // epilogue: 2 threads per row, each handles 2 chunks of 32 cols
    int row = tid & 127, half = tid >> 7;
    int m = m0 + row;
    bool act = m < M;
    float pv = 0.f;
    if (EPI == E_LSTM && act) pv = prevv[m];

#pragma unroll 1
    for (int qq = 0; qq < 2; qq++) {
        int q = half * 2 + qq;
        if (!act) continue;
        float r[32];
#pragma unroll
        for (int i = 0; i < 32; i++) r[i] = sC[row * SC_P + q * 32 + i];

        if (EPI == E_STOREH || EPI == E_BIASH) {
            size_t ob = (size_t)m * ldc + n0 + q * 32;
#pragma unroll
            for (int b = 0; b < 4; b++) {
                uint4 uo;
                __half2* op = (__half2*)&uo;
#pragma unroll
                for (int j = 0; j < 4; j++) {
                    float v0 = r[8 * b + 2 * j], v1 = r[8 * b + 2 * j + 1];
                    if (EPI == E_BIASH) {
                        v0 += aux[q * 32 + 8 * b + 2 * j];
                        v1 += aux[q * 32 + 8 * b + 2 * j + 1];
                    }
                    op[j] = __floats2half2_rn(v0, v1);
                }
                *(uint4*)(Oh + ob + b * 8) = uo;
            }
        } else {  // E_LSTM
            float g0v[32];
            const uint4* gp4 = (const uint4*)(G0 + (size_t)m * ldc + n0 + q * 32);
#pragma unroll
            for (int i = 0; i < 4; i++) {
                uint4 t = gp4[i];
                __half2* hp = (__half2*)&t;
#pragma unroll
                for (int j = 0; j < 4; j++) {
                    float2 f = __half22float2(hp[j]);
                    g0v[8 * i + 2 * j] = f.x;
                    g0v[8 * i + 2 * j + 1] = f.y;
                }
            }
            int jb = (n0 + q * 32) >> 2;
            float c8[8];
            {
                float4 c0 = *(const float4*)(cst + (size_t)m * 256 + jb);
                float4 c1 = *(const float4*)(cst + (size_t)m * 256 + jb + 4);
                c8[0] = c0.x; c8[1] = c0.y; c8[2] = c0.z; c8[3] = c0.w;
                c8[4] = c1.x; c8[5] = c1.y; c8[6] = c1.z; c8[7] = c1.w;
            }
            __half hh[8];
#pragma unroll
            for (int f = 0; f < 8; f++) {
                int b = 4 * f;
                float ig = sigm(r[b + 0] + g0v[b + 0] + pv * aux[q * 32 + b + 0]);
                float fg = sigm(r[b + 1] + g0v[b + 1] + pv * aux[q * 32 + b + 1]);
                float gg = tanhf(r[b + 2] + g0v[b + 2] + pv * aux[q * 32 + b + 2]);
                float og = sigm(r[b + 3] + g0v[b + 3] + pv * aux[q * 32 + b + 3]);
                float cn = fg * c8[f] + ig * gg;
                c8[f] = cn;
                hh[f] = __float2half_rn(og * tanhf(cn));
            }
            {
                float4 c0 = make_float4(c8[0], c8[1], c8[2], c8[3]);
                float4 c1 = make_float4(c8[4], c8[5], c8[6], c8[7]);
                *(float4*)(cst + (size_t)m * 256 + jb) = c0;
                *(float4*)(cst + (size_t)m * 256 + jb + 4) = c1;
            }
            uint4 uo;
            __half2* op = (__half2*)&uo;
            op[0] = __halves2half2(hh[0], hh[1]);
            op[1] = __halves2half2(hh[2], hh[3]);
            op[2] = __halves2half2(hh[4], hh[5]);
            op[3] = __halves2half2(hh[6], hh[7]);
            *(uint4*)(Oh + (size_t)m * 256 + jb) = uo;
        }
    }
}

// ---------------- CSR build ----------------
__global__ void zero_i_k(int* p, int n) {
    int i = blockIdx.x * 256 + threadIdx.x;
    if (i < n) p[i] = 0;
}
__global__ void zero_f_k(float* p, int n) {
    int i = blockIdx.x * 256 + threadIdx.x;
    if (i < n) p[i] = 0.f;
}
__global__ void count_k(const int* __restrict__ dst, int* __restrict__ deg, int E) {
    int e = blockIdx.x * 256 + threadIdx.x;
    if (e < E) atomicAdd(&deg[dst[e]], 1);
}
__global__ void scan_k(const int* __restrict__ deg, int* __restrict__ off, int* __restrict__ cur, int n) {
    __shared__ int s[1024];
    int t = threadIdx.x;
    int per = (n + 1023) >> 10;
    int b = t * per;
    int e = min(b + per, n);
    int sum = 0;
    for (int i = b; i < e; i++) sum += deg[i];
    s[t] = sum;
    __syncthreads();
    for (int d = 1; d < 1024; d <<= 1) {
        int v = (t >= d) ? s[t - d] : 0;
        __syncthreads();
        s[t] += v;
        __syncthreads();
    }
    int run = s[t] - sum;
    for (int i = b; i < e; i++) { off[i] = run; cur[i] = run; run += deg[i]; }
    if (t == 1023) off[n] = s[1023];
}
__global__ void scatter_k(const int* __restrict__ dst, int* __restrict__ cur, int* __restrict__ eidx, int E) {
    int e = blockIdx.x * 256 + threadIdx.x;
    if (e < E) {
        int p = atomicAdd(&cur[dst[e]], 1);
        eidx[p] = e;
    }
}

// ---------------- weight prep (single fp16 term) ----------------
__global__ void wsT_k(const float* __restrict__ w, __half* __restrict__ oh) {
    int n = blockIdx.x, k = threadIdx.x;
    oh[n * 256 + k] = __float2half_rn(w[k * 256 + n]);
}
__global__ void mlpb_k(const float* __restrict__ mw, __half* __restrict__ oh) {
    int n = blockIdx.x, k = threadIdx.x;
    oh[n * 256 + k] = __float2half_rn(mw[n * 257 + 1 + k]);
}
__global__ void wperm_k(const float* __restrict__ w, __half* __restrict__ oh) {
    int pg = blockIdx.x, k = threadIdx.x;
    int row = (pg & 3) * 256 + (pg >> 2);
    oh[(size_t)pg * 256 + k] = __float2half_rn(w[(size_t)row * 256 + k]);
}
__global__ void uvec2_k(const float* __restrict__ wih, const float* __restrict__ mw,
                        const float* __restrict__ bih, const float* __restrict__ bhh,
                        float* __restrict__ up, float* __restrict__ bsp) {
    int pg = blockIdx.x * 256 + threadIdx.x;
    int row = (pg & 3) * 256 + (pg >> 2);
    float s = 0.f;
    for (int k = 0; k < 256; k++) s += wih[(size_t)row * 256 + k] * mw[k * 257];
    up[pg] = s;
    bsp[pg] = bih[row] + bhh[row];
}
__global__ void xhalf_k(const float* __restrict__ x, __half* __restrict__ o, int n) {
    int i = blockIdx.x * 256 + threadIdx.x;
    if (i < n) o[i] = __float2half_rn(x[i]);
}

// ---------------- GAT edge kernels ----------------
__device__ __forceinline__ float lreluf(float v) { return v > 0.f ? v : 0.2f * v; }
__device__ __forceinline__ float eluf(float v) { return v > 0.f ? v : expm1f(v); }

__global__ void edge_logits_k(const __half* __restrict__ xl, const __half* __restrict__ xr,
                              const int* __restrict__ src, const int* __restrict__ dst,
                              const float* __restrict__ att, float* __restrict__ elog, int E) {
    __shared__ float satt[HID];
    int tid = threadIdx.x;
    satt[tid] = att[tid];
    __syncthreads();
    int lane = tid & 31, w = tid >> 5;
    int e = blockIdx.x * 8 + w;
    if (e >= E) return;
    int s = src[e], d = dst[e];
    uint4 va = *(const uint4*)(xl + (size_t)s * HID + lane * 8);
    uint4 vb = *(const uint4*)(xr + (size_t)d * HID + lane * 8);
    __half2* ha = (__half2*)&va;
    __half2* hb = (__half2*)&vb;
    const float* at = satt + lane * 8;
    float p = 0.f;
#pragma unroll
    for (int j = 0; j < 4; j++) {
        float2 fa = __half22float2(ha[j]);
        float2 fb = __half22float2(hb[j]);
        p += at[2 * j] * lreluf(fa.x + fb.x);
        p += at[2 * j + 1] * lreluf(fa.y + fb.y);
    }
    p += __shfl_xor_sync(0xffffffffu, p, 1);
    p += __shfl_xor_sync(0xffffffffu, p, 2);
    p += __shfl_xor_sync(0xffffffffu, p, 4);
    if ((lane & 7) == 0) elog[(size_t)e * NH + (lane >> 3)] = expf(p);
}

__global__ void aggregate_k(const __half* __restrict__ xl, const float* __restrict__ elog,
                            const int* __restrict__ src,
                            const int* __restrict__ off, const int* __restrict__ eidx,
                            const float* __restrict__ bias,
                            __half* __restrict__ o, int N) {
    int tid = threadIdx.x;
    int lane = tid & 31, w = tid >> 5;
    int n = blockIdx.x * 8 + w;
    if (n >= N) return;
    int beg = off[n], end = off[n + 1];
    int h = lane >> 3;
    float den = 0.f;
    for (int j = beg; j < end; j++) den += elog[(size_t)eidx[j] * NH + h];
    float rin = 1.f / den;
    float a[8];
#pragma unroll
    for (int i = 0; i < 8; i++) a[i] = 0.f;
    for (int j = beg; j < end; j++) {
        int e = eidx[j];
        float wg = elog[(size_t)e * NH + h] * rin;
        uint4 vv = *(const uint4*)(xl + (size_t)src[e] * HID + lane * 8);
        __half2* hv = (__half2*)&vv;
#pragma unroll
        for (int i = 0; i < 4; i++) {
            float2 f = __half22float2(hv[i]);
            a[2 * i] += wg * f.x;
            a[2 * i + 1] += wg * f.y;
        }
    }
    const float* bb = bias + lane * 8;
    uint4 uo;
    __half2* op = (__half2*)&uo;
#pragma unroll
    for (int i = 0; i < 4; i++)
        op[i] = __floats2half2_rn(eluf(a[2 * i] + bb[2 * i]), eluf(a[2 * i + 1] + bb[2 * i + 1]));
    *(uint4*)(o + (size_t)n * HID + lane * 8) = uo;
}

// ---------------- decoder small kernels ----------------
__global__ void rowdot_h(const __half* __restrict__ hi,
                         const float* __restrict__ w, const float* __restrict__ b,
                         float* __restrict__ prev, float* __restrict__ outp, int step, int N) {
    int wid = blockIdx.x * 8 + (threadIdx.x >> 5);
    int lane = threadIdx.x & 31;
    if (wid >= N) return;
    size_t base = (size_t)wid * HID;
    float s = 0.f;
#pragma unroll
    for (int i = 0; i < 8; i++) {
        int k = lane + i * 32;
        s += __half2float(hi[base + k]) * w[k];
    }
    for (int d = 16; d; d >>= 1) s += __shfl_xor_sync(0xffffffffu, s, d);
    if (lane == 0) {
        float t = s + b[0];
        prev[wid] = t;
        if (outp) outp[(size_t)wid * TOUT + step] = t;
    }
}

// ---------------- launch ----------------
extern "C" void kernel_launch(void* const* d_in, const int* in_sizes, int n_in,
                              void* d_out, int out_size) {
    const float* x     = (const float*)d_in[0];
    const int*   ei    = (const int*)d_in[1];
    const float* w_src = (const float*)d_in[2];
    const float* w_dst = (const float*)d_in[3];
    const float* att   = (const float*)d_in[4];
    const float* gbias = (const float*)d_in[5];
    const float* mlp_w = (const float*)d_in[6];
    const float* mlp_b = (const float*)d_in[7];
    const float* wih   = (const float*)d_in[8];
    const float* whh   = (const float*)d_in[9];
    const float* bih   = (const float*)d_in[10];
    const float* bhh   = (const float*)d_in[11];
    const float* initw = (const float*)d_in[12];
    const float* initb = (const float*)d_in[13];
    const float* outw  = (const float*)d_in[14];
    const float* outb  = (const float*)d_in[15];
    float* out = (float*)d_out;

    int N = in_sizes[0] / HID;
    int E = in_sizes[1] / 2;

    float *elog, *cst, *prev, *up, *bsp;
    int *deg, *off, *cur, *eidx;
    __half *xl, *xr, *s0, *hA, *hB, *cs, *G0;
    __half *wg, *mb, *wihW, *whhW;
    cudaGetSymbolAddress((void**)&xl, g_xl);
    cudaGetSymbolAddress((void**)&xr, g_xr);
    cudaGetSymbolAddress((void**)&elog, g_elog);
    cudaGetSymbolAddress((void**)&G0, g_G0);
    cudaGetSymbolAddress((void**)&cst, g_c);
    cudaGetSymbolAddress((void**)&prev, g_prev);
    cudaGetSymbolAddress((void**)&up, g_up);
    cudaGetSymbolAddress((void**)&bsp, g_bsp);
    cudaGetSymbolAddress((void**)&deg, g_deg);
    cudaGetSymbolAddress((void**)&off, g_off);
    cudaGetSymbolAddress((void**)&cur, g_cur);
    cudaGetSymbolAddress((void**)&eidx, g_eidx);
    cudaGetSymbolAddress((void**)&s0, g_s0);
    cudaGetSymbolAddress((void**)&hA, g_hA);
    cudaGetSymbolAddress((void**)&hB, g_hB);
    cudaGetSymbolAddress((void**)&cs, g_cs);
    cudaGetSymbolAddress((void**)&wg, g_wg);
    cudaGetSymbolAddress((void**)&mb, g_mb);
    cudaGetSymbolAddress((void**)&wihW, g_wih);
    cudaGetSymbolAddress((void**)&whhW, g_whh);

    cudaFuncSetAttribute(gemm_mma<E_STOREH>, cudaFuncAttributeMaxDynamicSharedMemorySize, SM_TOTAL);
    cudaFuncSetAttribute(gemm_mma<E_BIASH>, cudaFuncAttributeMaxDynamicSharedMemorySize, SM_TOTAL);
    cudaFuncSetAttribute(gemm_mma<E_LSTM>, cudaFuncAttributeMaxDynamicSharedMemorySize, SM_TOTAL);

    int eb = (E + 255) / 256;
    int nb = (N + 255) / 256;

    // CSR by destination
    zero_i_k<<<nb, 256>>>(deg, N);
    count_k<<<eb, 256>>>(ei + E, deg, E);
    scan_k<<<1, 1024>>>(deg, off, cur, N);
    scatter_k<<<eb, 256>>>(ei + E, cur, eidx, E);

    // weight prep
    for (int l = 0; l < NL; l++) {
        wsT_k<<<256, 256>>>(w_src + (size_t)l * 65536, wg + (size_t)(2 * l) * 65536);
        wsT_k<<<256, 256>>>(w_dst + (size_t)l * 65536, wg + (size_t)(2 * l + 1) * 65536);
    }
    mlpb_k<<<256, 256>>>(mlp_w, mb);
    wperm_k<<<1024, 256>>>(wih, wihW);
    wperm_k<<<1024, 256>>>(whh, whhW);
    uvec2_k<<<4, 256>>>(wih, mlp_w, bih, bhh, up, bsp);
    xhalf_k<<<(N * HID + 255) / 256, 256>>>(x, s0, N * HID);
    zero_f_k<<<(N * HID + 255) / 256, 256>>>(cst, N * HID);

    int mg = (N + 127) / 128;
    int egrid = (E + 7) / 8;
    int ngrid = (N + 7) / 8;

    // GAT layers
    __half* sh = s0;
    for (int l = 0; l < NL; l++) {
        gemm_mma<E_STOREH><<<dim3(mg, 2), 256, SM_TOTAL>>>(
            sh, wg + (size_t)(2 * l) * 65536,
            N, HID, nullptr, xl, nullptr, nullptr, nullptr, nullptr);
        gemm_mma<E_STOREH><<<dim3(mg, 2), 256, SM_TOTAL>>>(
            sh, wg + (size_t)(2 * l + 1) * 65536,
            N, HID, nullptr, xr, nullptr, nullptr, nullptr, nullptr);
        edge_logits_k<<<egrid, 256>>>(xl, xr, ei, ei + E, att + l * HID, elog, E);
        __half* dof = (l == 0) ? s0 : hA;
        aggregate_k<<<ngrid, 256>>>(xl, elog, ei, off, eidx, gbias + l * HID, dof, N);
        sh = dof;
    }
    // sh == hA == h0 (fp16)

    // decoder precompute
    gemm_mma<E_BIASH><<<dim3(mg, 2), 256, SM_TOTAL>>>(
        hA, mb, N, HID, mlp_b, cs, nullptr, nullptr, nullptr, nullptr);
    gemm_mma<E_BIASH><<<dim3(mg, 8), 256, SM_TOTAL>>>(
        cs, wihW, N, 1024, bsp, G0, nullptr, nullptr, nullptr, nullptr);
    rowdot_h<<<ngrid, 256>>>(hA, initw, initb, prev, nullptr, 0, N);

    // recurrent steps: h ping-pongs A <-> B
    for (int s = 0; s < TOUT; s++) {
        __half* inh = (s & 1) ? hB : hA;
        __half* oh = (s & 1) ? hA : hB;
        gemm_mma<E_LSTM><<<dim3(mg, 8), 256, SM_TOTAL>>>(
            inh, whhW, N, 1024, nullptr, oh, G0, up, prev, cst);
        rowdot_h<<<ngrid, 256>>>(oh, outw, outb, prev, out, s, N);
    }
}